// round 10
// baseline (speedup 1.0000x reference)
#include <cuda_runtime.h>
#include <cuda_bf16.h>
#include <cstdint>
#include <cstddef>

#define HIDC 512
#define NTOK 1024
#define BATCH 32
#define CEFF 1280

typedef __nv_bfloat16 bf16;

// ------------------------- scratch ---------------------------------------
__device__ float g_bqc[HIDC];
__device__ float g_rsum[(size_t)BATCH * NTOK];

__device__ bf16 g_Wq_h[HIDC * HIDC], g_Wk_h[HIDC * HIDC], g_Wv_h[HIDC * HIDC];
__device__ bf16 g_We_h[HIDC * CEFF];
__device__ bf16 g_WcT[HIDC * HIDC];
__device__ bf16 g_Wc_h[HIDC * HIDC], g_Wc_l[HIDC * HIDC];
__device__ bf16 g_Wqc_h[HIDC * HIDC];

__device__ bf16 g_XcT_h[(size_t)BATCH * NTOK * HIDC];
__device__ bf16 g_XcT_l[(size_t)BATCH * NTOK * HIDC];
__device__ bf16 g_XeT_h[(size_t)BATCH * NTOK * CEFF];

__device__ bf16    g_eff[(size_t)BATCH * NTOK * HIDC];   // [b][n][hid] bf16
__device__ uint8_t g_q8[(size_t)BATCH * NTOK * HIDC];    // [b][n][c] e4m3
__device__ uint8_t g_k8[(size_t)BATCH * NTOK * HIDC];    // [b][m][c] e4m3
__device__ uint8_t g_v8[(size_t)BATCH * HIDC * NTOK];    // [b][c][m] e4m3
__device__ uint8_t g_P8[(size_t)BATCH * NTOK * NTOK];    // [b][n][m] e4m3, exp/16

#define MMA_B16(D, A_, B_) \
    asm volatile("mma.sync.aligned.m16n8k16.row.col.f32.bf16.bf16.f32 " \
        "{%0,%1,%2,%3}, {%4,%5,%6,%7}, {%8,%9}, {%0,%1,%2,%3};" \
        : "+f"((D)[0]), "+f"((D)[1]), "+f"((D)[2]), "+f"((D)[3]) \
        : "r"((A_)[0]), "r"((A_)[1]), "r"((A_)[2]), "r"((A_)[3]), \
          "r"((B_)[0]), "r"((B_)[1]))

#define MMA_E4M3(D, A_, B_) \
    asm volatile("mma.sync.aligned.m16n8k32.row.col.f32.e4m3.e4m3.f32 " \
        "{%0,%1,%2,%3}, {%4,%5,%6,%7}, {%8,%9}, {%0,%1,%2,%3};" \
        : "+f"((D)[0]), "+f"((D)[1]), "+f"((D)[2]), "+f"((D)[3]) \
        : "r"((A_)[0]), "r"((A_)[1]), "r"((A_)[2]), "r"((A_)[3]), \
          "r"((B_)[0]), "r"((B_)[1]))

#define LDSM4(R0, R1, R2, R3, ADDR) \
    asm volatile("ldmatrix.sync.aligned.m8n8.x4.shared.b16 {%0,%1,%2,%3}, [%4];" \
        : "=r"(R0), "=r"(R1), "=r"(R2), "=r"(R3) : "r"(ADDR))

__device__ __forceinline__ uint32_t smem_u32(const void* p) {
    uint32_t a;
    asm("{ .reg .u64 t; cvta.to.shared.u64 t, %1; cvt.u32.u64 %0, t; }" : "=r"(a) : "l"(p));
    return a;
}
__device__ __forceinline__ void cp16(uint32_t dst, const void* src) {
    asm volatile("cp.async.cg.shared.global [%0], [%1], 16;" :: "r"(dst), "l"(src));
}
__device__ __forceinline__ void cp_commit() {
    asm volatile("cp.async.commit_group;" ::: "memory");
}
template<int N> __device__ __forceinline__ void cp_wait() {
    asm volatile("cp.async.wait_group %0;" :: "n"(N) : "memory");
}
// pack two fp32 -> e4m3x2 (lo, hi)
__device__ __forceinline__ uint16_t pack_e4m3(float lo, float hi) {
    uint16_t r;
    asm("cvt.rn.satfinite.e4m3x2.f32 %0, %1, %2;" : "=h"(r) : "f"(hi), "f"(lo));
    return r;
}

#define TILEB 18432   // 128 rows * 144B row-stride (128B data + 16B pad)

// ---------------------------------------------------------------------------
// HMMA/QMMA GEMM, 3-stage cp.async, byte-granular K (128B chunk = 64 bf16
// or 128 fp8 K-elems). ADT: 0 = bf16 (m16n8k16), 1 = e4m3 (m16n8k32).
// C[M0+128, N0+128] = sum_K A[m,k] * B[n,k]  (both K-major, strides in BYTES)
// SPLIT (bf16 only) adds Ah*Bl + Al*Bh.  BIASM: 0 none, 1 bias[row], 2 bias[col]
// OUTM: 0 fp32 +bias | 1 bf16 +bias | 5 e4m3 +bias
//       3 e4m3 exp(D)/16 + fp32 rowsum atomics | 4 fp32 RMW += 16*gamma/rowsum[col]*D
// ---------------------------------------------------------------------------
template<int ADT, bool SPLIT, int BIASM, int OUTM>
__global__ __launch_bounds__(256) void mma_gemm(
    const uint8_t* __restrict__ Ah, const uint8_t* __restrict__ Al,
    const uint8_t* __restrict__ Bh, const uint8_t* __restrict__ Bl,
    int ldaB, int ldbB, size_t sAB, size_t sBB,
    void* __restrict__ Cout, int ldc, size_t sC,
    const float* __restrict__ bias, const float* __restrict__ gamma, int KB)
{
    extern __shared__ char dynsm[];
    constexpr int STAGE = SPLIT ? 4 * TILEB : 2 * TILEB;
    const uint32_t sm0 = smem_u32(dynsm);

    const int tid = threadIdx.x;
    const int wid = tid >> 5;
    const int lid = tid & 31;
    const int wm = wid & 1;
    const int wn = wid >> 1;
    const int g  = lid >> 2;
    const int tc = (lid & 3) * 2;

    const int M0 = blockIdx.y * 128;
    const int N0 = blockIdx.x * 128;
    const int b  = blockIdx.z;

    const uint8_t* pA = Ah + (size_t)b * sAB + (size_t)M0 * ldaB;
    const uint8_t* pB = Bh + (size_t)b * sBB + (size_t)N0 * ldbB;
    const uint8_t* pAl = SPLIT ? (Al + (size_t)b * sAB + (size_t)M0 * ldaB) : nullptr;
    const uint8_t* pBl = SPLIT ? (Bl + (size_t)b * sBB + (size_t)N0 * ldbB) : nullptr;

    // ldmatrix per-thread byte offsets within a stage (144B row stride)
    const int l8  = lid & 7;
    const int mi1 = (lid >> 3) & 1;
    const int mi2 = (lid >> 4) & 1;
    const uint32_t offA = (uint32_t)((wm * 64 + mi1 * 8 + l8) * 144 + mi2 * 16);
    const uint32_t offB = (uint32_t)((wn * 32 + mi2 * 8 + l8) * 144 + mi1 * 16);

    float acc[4][4][4];
    #pragma unroll
    for (int i = 0; i < 4; i++)
        #pragma unroll
        for (int j = 0; j < 4; j++)
            #pragma unroll
            for (int r = 0; r < 4; r++) acc[i][j][r] = 0.f;

    const int nk = KB >> 7;

    auto copy_stage = [&](int buf, int kt) {
        const int k0 = kt << 7;
        const uint32_t sb = sm0 + buf * STAGE;
        #pragma unroll
        for (int s = 0; s < 4; s++) {
            const int i = tid + s * 256;
            const int r = i >> 3, c = (i & 7) * 16;
            const uint32_t so = (uint32_t)(r * 144 + c);
            cp16(sb + so,         pA + (size_t)r * ldaB + k0 + c);
            cp16(sb + TILEB + so, pB + (size_t)r * ldbB + k0 + c);
            if (SPLIT) {
                cp16(sb + 2 * TILEB + so, pAl + (size_t)r * ldaB + k0 + c);
                cp16(sb + 3 * TILEB + so, pBl + (size_t)r * ldbB + k0 + c);
            }
        }
        cp_commit();
    };

    copy_stage(0, 0);
    copy_stage(1, 1);      // all our nk >= 4

    int buf = 0;
    for (int kt = 0; kt < nk; kt++) {
        if (kt + 2 < nk) {
            int nb = buf + 2; if (nb >= 3) nb -= 3;
            copy_stage(nb, kt + 2);
            cp_wait<2>();
        } else if (kt + 1 < nk) {
            cp_wait<1>();
        } else {
            cp_wait<0>();
        }
        __syncthreads();

        const uint32_t sb = sm0 + buf * STAGE;
        #pragma unroll
        for (int ks = 0; ks < 4; ks++) {           // 4 x 32-byte K sub-steps
            uint32_t a[4][4], bb[4][2];
            #pragma unroll
            for (int mt = 0; mt < 4; mt++)
                LDSM4(a[mt][0], a[mt][1], a[mt][2], a[mt][3],
                      sb + offA + mt * 2304 + ks * 32);
            #pragma unroll
            for (int p = 0; p < 2; p++)
                LDSM4(bb[2 * p][0], bb[2 * p][1], bb[2 * p + 1][0], bb[2 * p + 1][1],
                      sb + TILEB + offB + p * 2304 + ks * 32);
            #pragma unroll
            for (int mt = 0; mt < 4; mt++)
                #pragma unroll
                for (int nt = 0; nt < 4; nt++) {
                    if (ADT == 0) { MMA_B16(acc[mt][nt], a[mt], bb[nt]); }
                    else          { MMA_E4M3(acc[mt][nt], a[mt], bb[nt]); }
                }
            if (SPLIT) {
                uint32_t al[4][4], bl[4][2];
                #pragma unroll
                for (int mt = 0; mt < 4; mt++)
                    LDSM4(al[mt][0], al[mt][1], al[mt][2], al[mt][3],
                          sb + 2 * TILEB + offA + mt * 2304 + ks * 32);
                #pragma unroll
                for (int p = 0; p < 2; p++)
                    LDSM4(bl[2 * p][0], bl[2 * p][1], bl[2 * p + 1][0], bl[2 * p + 1][1],
                          sb + 3 * TILEB + offB + p * 2304 + ks * 32);
                #pragma unroll
                for (int mt = 0; mt < 4; mt++)
                    #pragma unroll
                    for (int nt = 0; nt < 4; nt++) {
                        MMA_B16(acc[mt][nt], a[mt], bl[nt]);
                        MMA_B16(acc[mt][nt], al[mt], bb[nt]);
                    }
            }
        }
        __syncthreads();
        if (++buf == 3) buf = 0;
    }

    // ---------------- epilogue ----------------
    if (OUTM == 3) {
        // exp, write e4m3 P/16, accumulate fp32 rowsums
        __shared__ float srow[128];
        float* rs = const_cast<float*>(bias) + (size_t)b * NTOK;
        if (tid < 128) srow[tid] = 0.f;
        __syncthreads();
        uint8_t* C = (uint8_t*)Cout + (size_t)b * sC;
        #pragma unroll
        for (int mt = 0; mt < 4; mt++) {
            const int grow = M0 + wm * 64 + mt * 16 + g;
            float rp0 = 0.f, rp1 = 0.f;
            #pragma unroll
            for (int nt = 0; nt < 4; nt++) {
                const int gcol = N0 + wn * 32 + nt * 8 + tc;
                float e0 = __expf(acc[mt][nt][0]);
                float e1 = __expf(acc[mt][nt][1]);
                float e2 = __expf(acc[mt][nt][2]);
                float e3 = __expf(acc[mt][nt][3]);
                *(uint16_t*)(C + (size_t)grow * ldc + gcol) =
                    pack_e4m3(e0 * 0.0625f, e1 * 0.0625f);
                *(uint16_t*)(C + (size_t)(grow + 8) * ldc + gcol) =
                    pack_e4m3(e2 * 0.0625f, e3 * 0.0625f);
                rp0 += e0 + e1;
                rp1 += e2 + e3;
            }
            rp0 += __shfl_xor_sync(0xFFFFFFFFu, rp0, 1);
            rp0 += __shfl_xor_sync(0xFFFFFFFFu, rp0, 2);
            rp1 += __shfl_xor_sync(0xFFFFFFFFu, rp1, 1);
            rp1 += __shfl_xor_sync(0xFFFFFFFFu, rp1, 2);
            if ((lid & 3) == 0) {
                atomicAdd(&srow[wm * 64 + mt * 16 + g], rp0);
                atomicAdd(&srow[wm * 64 + mt * 16 + 8 + g], rp1);
            }
        }
        __syncthreads();
        if (tid < 128) atomicAdd(rs + M0 + tid, srow[tid]);
        return;
    }

    const float gm = (OUTM == 4) ? gamma[0] * 16.0f : 0.f;  // x16: P stored /16
    #pragma unroll
    for (int mt = 0; mt < 4; mt++) {
        #pragma unroll
        for (int nt = 0; nt < 4; nt++) {
            const int grow = M0 + wm * 64 + mt * 16 + g;
            const int gcol = N0 + wn * 32 + nt * 8 + tc;
            float d0 = acc[mt][nt][0], d1 = acc[mt][nt][1];
            float d2 = acc[mt][nt][2], d3 = acc[mt][nt][3];

            if (OUTM == 0 || OUTM == 1 || OUTM == 5) {
                if (BIASM == 1) {
                    float br0 = __ldg(bias + grow), br1 = __ldg(bias + grow + 8);
                    d0 += br0; d1 += br0; d2 += br1; d3 += br1;
                } else if (BIASM == 2) {
                    float bc0 = __ldg(bias + gcol), bc1 = __ldg(bias + gcol + 1);
                    d0 += bc0; d1 += bc1; d2 += bc0; d3 += bc1;
                }
            }

            if (OUTM == 0) {
                float* C = (float*)Cout + (size_t)b * sC;
                *(float2*)(C + (size_t)grow * ldc + gcol) = make_float2(d0, d1);
                *(float2*)(C + (size_t)(grow + 8) * ldc + gcol) = make_float2(d2, d3);
            } else if (OUTM == 1) {
                bf16* C = (bf16*)Cout + (size_t)b * sC;
                *(__nv_bfloat162*)(C + (size_t)grow * ldc + gcol) = __floats2bfloat162_rn(d0, d1);
                *(__nv_bfloat162*)(C + (size_t)(grow + 8) * ldc + gcol) = __floats2bfloat162_rn(d2, d3);
            } else if (OUTM == 5) {
                uint8_t* C = (uint8_t*)Cout + (size_t)b * sC;
                *(uint16_t*)(C + (size_t)grow * ldc + gcol) = pack_e4m3(d0, d1);
                *(uint16_t*)(C + (size_t)(grow + 8) * ldc + gcol) = pack_e4m3(d2, d3);
            } else { // OUTM == 4
                const float* rs = bias + (size_t)b * NTOK;
                const float s0 = gm / __ldg(rs + gcol);
                const float s1 = gm / __ldg(rs + gcol + 1);
                float* C = (float*)Cout + (size_t)b * sC;
                float2 c0 = *(float2*)(C + (size_t)grow * ldc + gcol);
                float2 c1 = *(float2*)(C + (size_t)(grow + 8) * ldc + gcol);
                c0.x += s0 * d0; c0.y += s1 * d1;
                c1.x += s0 * d2; c1.y += s1 * d3;
                *(float2*)(C + (size_t)grow * ldc + gcol) = c0;
                *(float2*)(C + (size_t)(grow + 8) * ldc + gcol) = c1;
            }
        }
    }
}

// transpose fp32 [b][C][1024] -> bf16 hi(/lo) [b][1024][C]
__global__ __launch_bounds__(256) void transpose_split(
    const float* __restrict__ in, bf16* __restrict__ hi, bf16* __restrict__ lo, int C)
{
    __shared__ float t[32][33];
    const int c0 = blockIdx.x * 32, n0 = blockIdx.y * 32, b = blockIdx.z;
    const float* pin = in + (size_t)b * C * NTOK;
    const int tx = threadIdx.x & 31, ty = threadIdx.x >> 5;
    #pragma unroll
    for (int i = 0; i < 4; i++)
        t[ty + i * 8][tx] = pin[(size_t)(c0 + ty + i * 8) * NTOK + n0 + tx];
    __syncthreads();
    #pragma unroll
    for (int i = 0; i < 4; i++) {
        float x = t[tx][ty + i * 8];
        bf16 h = __float2bfloat16(x);
        size_t o = (size_t)b * NTOK * C + (size_t)(n0 + ty + i * 8) * C + c0 + tx;
        hi[o] = h;
        if (lo) lo[o] = __float2bfloat16(x - __bfloat162float(h));
    }
}

__global__ __launch_bounds__(256) void transpose_wc(
    const float* __restrict__ Wc, bf16* __restrict__ WcT)
{
    __shared__ float t[32][33];
    const int c0 = blockIdx.x * 32, r0 = blockIdx.y * 32;
    const int tx = threadIdx.x & 31, ty = threadIdx.x >> 5;
    #pragma unroll
    for (int i = 0; i < 4; i++)
        t[ty + i * 8][tx] = Wc[(size_t)(r0 + ty + i * 8) * HIDC + c0 + tx];
    __syncthreads();
    #pragma unroll
    for (int i = 0; i < 4; i++)
        WcT[(size_t)(c0 + ty + i * 8) * HIDC + r0 + tx] = __float2bfloat16(t[tx][ty + i * 8]);
}

__global__ void cast_weights(
    const float* __restrict__ Wq, const float* __restrict__ Wk,
    const float* __restrict__ Wv, const float* __restrict__ Wc,
    const float* __restrict__ We,
    bf16* __restrict__ oq, bf16* __restrict__ ok, bf16* __restrict__ ov,
    bf16* __restrict__ ch, bf16* __restrict__ cl, bf16* __restrict__ oe)
{
    const int i = blockIdx.x * 256 + threadIdx.x;
    const int w = blockIdx.y;
    if (w == 4) {
        if (i < HIDC * CEFF) oe[i] = __float2bfloat16(We[i]);
        return;
    }
    if (i >= HIDC * HIDC) return;
    if (w == 0)      oq[i] = __float2bfloat16(Wq[i]);
    else if (w == 1) ok[i] = __float2bfloat16(Wk[i]);
    else if (w == 2) ov[i] = __float2bfloat16(Wv[i]);
    else {
        float x = Wc[i];
        bf16 h = __float2bfloat16(x);
        ch[i] = h;
        cl[i] = __float2bfloat16(x - __bfloat162float(h));
    }
}

__global__ void combine_qbias(
    const float* __restrict__ Wq, const float* __restrict__ bcnn,
    const float* __restrict__ bq, float* __restrict__ bqc)
{
    const int o = blockIdx.x * 8 + (threadIdx.x >> 5);
    const int l = threadIdx.x & 31;
    float s = 0.f;
    for (int c = l; c < HIDC; c += 32) s += Wq[(size_t)o * HIDC + c] * bcnn[c];
    #pragma unroll
    for (int d = 16; d; d >>= 1) s += __shfl_xor_sync(0xFFFFFFFFu, s, d);
    if (l == 0) bqc[o] = s + bq[o];
}

// ------------------------------ launch ------------------------------------
extern "C" void kernel_launch(void* const* d_in, const int* in_sizes, int n_in,
                              void* d_out, int out_size)
{
    const float* xc = (const float*)d_in[0];
    const float* xe = (const float*)d_in[1];
    const float* Wc = (const float*)d_in[2];
    const float* bc = (const float*)d_in[3];
    const float* We = (const float*)d_in[4];
    const float* be = (const float*)d_in[5];
    const float* Wq = (const float*)d_in[6];
    const float* bq = (const float*)d_in[7];
    const float* Wk = (const float*)d_in[8];
    const float* bk = (const float*)d_in[9];
    const float* Wv = (const float*)d_in[10];
    const float* bv = (const float*)d_in[11];
    const float* gamma = (const float*)d_in[12];
    float* out = (float*)d_out;

    float *p_bqc, *p_rsum;
    bf16 *p_Wq_h, *p_Wk_h, *p_Wv_h, *p_We_h, *p_WcT, *p_Wc_h, *p_Wc_l, *p_Wqc_h;
    bf16 *p_XcT_h, *p_XcT_l, *p_XeT_h, *p_eff;
    uint8_t *p_q8, *p_k8, *p_v8, *p_P8;
    cudaGetSymbolAddress((void**)&p_bqc, g_bqc);
    cudaGetSymbolAddress((void**)&p_rsum, g_rsum);
    cudaGetSymbolAddress((void**)&p_Wq_h, g_Wq_h);
    cudaGetSymbolAddress((void**)&p_Wk_h, g_Wk_h);
    cudaGetSymbolAddress((void**)&p_Wv_h, g_Wv_h);
    cudaGetSymbolAddress((void**)&p_We_h, g_We_h);
    cudaGetSymbolAddress((void**)&p_WcT, g_WcT);
    cudaGetSymbolAddress((void**)&p_Wc_h, g_Wc_h);
    cudaGetSymbolAddress((void**)&p_Wc_l, g_Wc_l);
    cudaGetSymbolAddress((void**)&p_Wqc_h, g_Wqc_h);
    cudaGetSymbolAddress((void**)&p_XcT_h, g_XcT_h);
    cudaGetSymbolAddress((void**)&p_XcT_l, g_XcT_l);
    cudaGetSymbolAddress((void**)&p_XeT_h, g_XeT_h);
    cudaGetSymbolAddress((void**)&p_eff, g_eff);
    cudaGetSymbolAddress((void**)&p_q8, g_q8);
    cudaGetSymbolAddress((void**)&p_k8, g_k8);
    cudaGetSymbolAddress((void**)&p_v8, g_v8);
    cudaGetSymbolAddress((void**)&p_P8, g_P8);

    const int SM_PLAIN = 3 * 2 * TILEB;   // 110592
    const int SM_SPLIT = 3 * 4 * TILEB;   // 221184
    cudaFuncSetAttribute(mma_gemm<0, true, 1, 0>, cudaFuncAttributeMaxDynamicSharedMemorySize, SM_SPLIT);
    cudaFuncSetAttribute(mma_gemm<0, false, 0, 1>, cudaFuncAttributeMaxDynamicSharedMemorySize, SM_PLAIN);
    cudaFuncSetAttribute(mma_gemm<0, false, 2, 1>, cudaFuncAttributeMaxDynamicSharedMemorySize, SM_PLAIN);
    cudaFuncSetAttribute(mma_gemm<0, false, 2, 5>, cudaFuncAttributeMaxDynamicSharedMemorySize, SM_PLAIN);
    cudaFuncSetAttribute(mma_gemm<0, false, 1, 5>, cudaFuncAttributeMaxDynamicSharedMemorySize, SM_PLAIN);
    cudaFuncSetAttribute(mma_gemm<1, false, 0, 3>, cudaFuncAttributeMaxDynamicSharedMemorySize, SM_PLAIN);
    cudaFuncSetAttribute(mma_gemm<1, false, 0, 4>, cudaFuncAttributeMaxDynamicSharedMemorySize, SM_PLAIN);

    // byte strides
    const int    ldH  = HIDC * 2;                       // 1024 B (bf16 rows of 512)
    const int    ldE  = CEFF * 2;                       // 2560 B
    const size_t sXcB = (size_t)NTOK * HIDC * 2;
    const size_t sXeB = (size_t)NTOK * CEFF * 2;
    // element strides (outputs)
    const size_t sO   = (size_t)HIDC * NTOK;            // fp32 out
    const size_t sQ8  = (size_t)NTOK * HIDC;            // bytes
    const size_t sV8  = (size_t)HIDC * NTOK;
    const size_t sP8  = (size_t)NTOK * NTOK;

    // prep
    cast_weights<<<dim3(2560, 5), 256>>>(Wq, Wk, Wv, Wc, We,
        p_Wq_h, p_Wk_h, p_Wv_h, p_Wc_h, p_Wc_l, p_We_h);
    transpose_wc<<<dim3(16, 16), 256>>>(Wc, p_WcT);
    combine_qbias<<<64, 256>>>(Wq, bc, bq, p_bqc);

    // fold Wqc = Wq @ Wc (bf16 out)
    mma_gemm<0, false, 0, 1><<<dim3(4, 4, 1), 256, SM_PLAIN>>>(
        (const uint8_t*)p_Wq_h, nullptr, (const uint8_t*)p_WcT, nullptr,
        ldH, ldH, 0, 0, p_Wqc_h, HIDC, 0, nullptr, nullptr, ldH);

    // activation transposes
    transpose_split<<<dim3(16, 32, BATCH), 256>>>(xc, p_XcT_h, p_XcT_l, HIDC);
    transpose_split<<<dim3(40, 32, BATCH), 256>>>(xe, p_XeT_h, nullptr, CEFF);

    // cnn_proj (split bf16) -> d_out fp32 [b][c][n]
    mma_gemm<0, true, 1, 0><<<dim3(8, 4, BATCH), 256, SM_SPLIT>>>(
        (const uint8_t*)p_Wc_h, (const uint8_t*)p_Wc_l,
        (const uint8_t*)p_XcT_h, (const uint8_t*)p_XcT_l,
        ldH, ldH, 0, sXcB, out, NTOK, sO, bc, nullptr, ldH);

    // q[b][n][c] -> e4m3
    mma_gemm<0, false, 2, 5><<<dim3(4, 8, BATCH), 256, SM_PLAIN>>>(
        (const uint8_t*)p_XcT_h, nullptr, (const uint8_t*)p_Wqc_h, nullptr,
        ldH, ldH, sXcB, 0, p_q8, HIDC, sQ8, p_bqc, nullptr, ldH);

    // eff[b][n][hid] bf16 = XeT @ We^T + be
    mma_gemm<0, false, 2, 1><<<dim3(4, 8, BATCH), 256, SM_PLAIN>>>(
        (const uint8_t*)p_XeT_h, nullptr, (const uint8_t*)p_We_h, nullptr,
        ldE, ldE, sXeB, 0, p_eff, HIDC, (size_t)NTOK * HIDC, be, nullptr, ldE);

    // k[b][m][c] -> e4m3
    mma_gemm<0, false, 2, 5><<<dim3(4, 8, BATCH), 256, SM_PLAIN>>>(
        (const uint8_t*)p_eff, nullptr, (const uint8_t*)p_Wk_h, nullptr,
        ldH, ldH, sXcB, 0, p_k8, HIDC, sQ8, bk, nullptr, ldH);

    // v[b][c][m] -> e4m3
    mma_gemm<0, false, 1, 5><<<dim3(8, 4, BATCH), 256, SM_PLAIN>>>(
        (const uint8_t*)p_Wv_h, nullptr, (const uint8_t*)p_eff, nullptr,
        ldH, ldH, 0, sXcB, p_v8, NTOK, sV8, bv, nullptr, ldH);

    // fused fp8 logits + exp + rowsum -> P8 (exp/16)
    cudaMemsetAsync(p_rsum, 0, (size_t)BATCH * NTOK * sizeof(float));
    mma_gemm<1, false, 0, 3><<<dim3(8, 8, BATCH), 256, SM_PLAIN>>>(
        p_q8, nullptr, p_k8, nullptr,
        HIDC, HIDC, sQ8, sQ8, p_P8, NTOK, sP8, p_rsum, nullptr, HIDC);

    // fp8 PV: out[b][c][n] += 16*gamma/rowsum[n] * (v8 @ P8^T)
    mma_gemm<1, false, 0, 4><<<dim3(8, 4, BATCH), 256, SM_PLAIN>>>(
        p_v8, nullptr, p_P8, nullptr,
        NTOK, NTOK, sV8, sP8, out, NTOK, sO, p_rsum, gamma, NTOK);
}

// round 12
// speedup vs baseline: 1.1347x; 1.1347x over previous
#include <cuda_runtime.h>
#include <cuda_bf16.h>
#include <cstdint>
#include <cstddef>

#define HIDC 512
#define NTOK 1024
#define BATCH 32
#define CEFF 1280

typedef __nv_bfloat16 bf16;

// ------------------------- scratch ---------------------------------------
__device__ float g_bqc[HIDC];
__device__ float g_rsum[(size_t)BATCH * NTOK];

__device__ bf16 g_Wq_h[HIDC * HIDC], g_Wk_h[HIDC * HIDC], g_Wv_h[HIDC * HIDC];
__device__ bf16 g_We_h[HIDC * CEFF];
__device__ bf16 g_WcT[HIDC * HIDC];
__device__ bf16 g_Wc_h[HIDC * HIDC], g_Wc_l[HIDC * HIDC];
__device__ bf16 g_Wqc_h[HIDC * HIDC];

__device__ bf16 g_XcT_h[(size_t)BATCH * NTOK * HIDC];
__device__ bf16 g_XcT_l[(size_t)BATCH * NTOK * HIDC];
__device__ bf16 g_XeT_h[(size_t)BATCH * NTOK * CEFF];

__device__ bf16 g_eff[(size_t)BATCH * NTOK * HIDC];
__device__ bf16 g_qb[(size_t)BATCH * NTOK * HIDC];
__device__ bf16 g_kb[(size_t)BATCH * NTOK * HIDC];
__device__ bf16 g_vb[(size_t)BATCH * HIDC * NTOK];
__device__ bf16 g_P[(size_t)BATCH * NTOK * NTOK];

#define MMA_B16(D, A_, B_) \
    asm volatile("mma.sync.aligned.m16n8k16.row.col.f32.bf16.bf16.f32 " \
        "{%0,%1,%2,%3}, {%4,%5,%6,%7}, {%8,%9}, {%0,%1,%2,%3};" \
        : "+f"((D)[0]), "+f"((D)[1]), "+f"((D)[2]), "+f"((D)[3]) \
        : "r"((A_)[0]), "r"((A_)[1]), "r"((A_)[2]), "r"((A_)[3]), \
          "r"((B_)[0]), "r"((B_)[1]))

#define LDSM4(R0, R1, R2, R3, ADDR) \
    asm volatile("ldmatrix.sync.aligned.m8n8.x4.shared.b16 {%0,%1,%2,%3}, [%4];" \
        : "=r"(R0), "=r"(R1), "=r"(R2), "=r"(R3) : "r"(ADDR))

__device__ __forceinline__ uint32_t smem_u32(const void* p) {
    uint32_t a;
    asm("{ .reg .u64 t; cvta.to.shared.u64 t, %1; cvt.u32.u64 %0, t; }" : "=r"(a) : "l"(p));
    return a;
}
__device__ __forceinline__ void cp16(uint32_t dst, const void* src) {
    asm volatile("cp.async.cg.shared.global [%0], [%1], 16;" :: "r"(dst), "l"(src));
}
__device__ __forceinline__ void cp_commit() {
    asm volatile("cp.async.commit_group;" ::: "memory");
}
template<int N> __device__ __forceinline__ void cp_wait() {
    asm volatile("cp.async.wait_group %0;" :: "n"(N) : "memory");
}

#define TILEB 18432   // 128 rows * 72 elems * 2B

#define MAINLOOP_BODY(SBASE) \
    _Pragma("unroll") \
    for (int ks = 0; ks < 64; ks += 16) { \
        uint32_t a[4][4], bb[4][2]; \
        _Pragma("unroll") \
        for (int mt = 0; mt < 4; mt++) \
            LDSM4(a[mt][0], a[mt][1], a[mt][2], a[mt][3], \
                  (SBASE) + offA + mt * 2304 + ks * 2); \
        _Pragma("unroll") \
        for (int p = 0; p < 2; p++) \
            LDSM4(bb[2 * p][0], bb[2 * p][1], bb[2 * p + 1][0], bb[2 * p + 1][1], \
                  (SBASE) + TILEB + offB + p * 2304 + ks * 2); \
        _Pragma("unroll") \
        for (int mt = 0; mt < 4; mt++) \
            _Pragma("unroll") \
            for (int nt = 0; nt < 4; nt++) \
                MMA_B16(acc[mt][nt], a[mt], bb[nt]); \
    }

// ---------------------------------------------------------------------------
// bf16 HMMA GEMM, 3-stage cp.async pipeline, BK=64, ldmatrix fragments.
// C[M0+128, N0+128] = sum_K A[m,k] * B[n,k]  (both K-major)
// SPLIT adds Ah*Bl + Al*Bh.  BIASM: 0 none, 1 bias[row], 2 bias[col]
// OUTM: 0 fp32 row-major (+bias) | 1 bf16 row-major (+bias)
//       3 bf16 exp(D) + rowsum atomics | 4 fp32 RMW += gamma/rowsum[col]*D
// ---------------------------------------------------------------------------
template<bool SPLIT, int BIASM, int OUTM>
__global__ __launch_bounds__(256) void mma_gemm(
    const bf16* __restrict__ Ah, const bf16* __restrict__ Al,
    const bf16* __restrict__ Bh, const bf16* __restrict__ Bl,
    int lda, int ldb, size_t sA, size_t sB,
    void* __restrict__ Cout, int ldc, size_t sC,
    const float* __restrict__ bias, const float* __restrict__ gamma, int K)
{
    extern __shared__ char dynsm[];
    constexpr int STAGE = SPLIT ? 4 * TILEB : 2 * TILEB;
    const uint32_t sm0 = smem_u32(dynsm);

    const int tid = threadIdx.x;
    const int wid = tid >> 5;
    const int lid = tid & 31;
    const int wm = wid & 1;
    const int wn = wid >> 1;
    const int g  = lid >> 2;
    const int tc = (lid & 3) * 2;

    const int M0 = blockIdx.y * 128;
    const int N0 = blockIdx.x * 128;
    const int b  = blockIdx.z;

    const bf16* pA = Ah + (size_t)b * sA + (size_t)M0 * lda;
    const bf16* pB = Bh + (size_t)b * sB + (size_t)N0 * ldb;
    const bf16* pAl = SPLIT ? (Al + (size_t)b * sA + (size_t)M0 * lda) : nullptr;
    const bf16* pBl = SPLIT ? (Bl + (size_t)b * sB + (size_t)N0 * ldb) : nullptr;

    const int l8  = lid & 7;
    const int mi1 = (lid >> 3) & 1;
    const int mi2 = (lid >> 4) & 1;
    const uint32_t offA = (uint32_t)(((wm * 64 + mi1 * 8 + l8) * 72 + mi2 * 8) * 2);
    const uint32_t offB = (uint32_t)(((wn * 32 + mi2 * 8 + l8) * 72 + mi1 * 8) * 2);

    float acc[4][4][4];
    #pragma unroll
    for (int i = 0; i < 4; i++)
        #pragma unroll
        for (int j = 0; j < 4; j++)
            #pragma unroll
            for (int r = 0; r < 4; r++) acc[i][j][r] = 0.f;

    const int nk = K >> 6;

    auto copy_stage = [&](int buf, int kt) {
        const int k0 = kt << 6;
        const uint32_t sb = sm0 + buf * STAGE;
        #pragma unroll
        for (int s = 0; s < 4; s++) {
            const int i = tid + s * 256;
            const int r = i >> 3, c = (i & 7) * 8;
            const uint32_t so = (uint32_t)((r * 72 + c) * 2);
            cp16(sb + so,         pA + (size_t)r * lda + k0 + c);
            cp16(sb + TILEB + so, pB + (size_t)r * ldb + k0 + c);
            if (SPLIT) {
                cp16(sb + 2 * TILEB + so, pAl + (size_t)r * lda + k0 + c);
                cp16(sb + 3 * TILEB + so, pBl + (size_t)r * ldb + k0 + c);
            }
        }
        cp_commit();
    };

    copy_stage(0, 0);
    copy_stage(1, 1);

    int buf = 0;
    for (int kt = 0; kt < nk; kt++) {
        if (kt + 2 < nk) {
            int nb = buf + 2; if (nb >= 3) nb -= 3;
            copy_stage(nb, kt + 2);
            cp_wait<2>();
        } else if (kt + 1 < nk) {
            cp_wait<1>();
        } else {
            cp_wait<0>();
        }
        __syncthreads();

        const uint32_t sb = sm0 + buf * STAGE;
        MAINLOOP_BODY(sb)
        if (SPLIT) {
            #pragma unroll
            for (int ks = 0; ks < 64; ks += 16) {
                uint32_t a[4][4], bb[4][2], al[4][4], bl[4][2];
                #pragma unroll
                for (int mt = 0; mt < 4; mt++) {
                    LDSM4(a[mt][0], a[mt][1], a[mt][2], a[mt][3],
                          sb + offA + mt * 2304 + ks * 2);
                    LDSM4(al[mt][0], al[mt][1], al[mt][2], al[mt][3],
                          sb + 2 * TILEB + offA + mt * 2304 + ks * 2);
                }
                #pragma unroll
                for (int p = 0; p < 2; p++) {
                    LDSM4(bb[2 * p][0], bb[2 * p][1], bb[2 * p + 1][0], bb[2 * p + 1][1],
                          sb + TILEB + offB + p * 2304 + ks * 2);
                    LDSM4(bl[2 * p][0], bl[2 * p][1], bl[2 * p + 1][0], bl[2 * p + 1][1],
                          sb + 3 * TILEB + offB + p * 2304 + ks * 2);
                }
                #pragma unroll
                for (int mt = 0; mt < 4; mt++)
                    #pragma unroll
                    for (int nt = 0; nt < 4; nt++) {
                        MMA_B16(acc[mt][nt], a[mt], bl[nt]);
                        MMA_B16(acc[mt][nt], al[mt], bb[nt]);
                    }
            }
        }
        __syncthreads();
        if (++buf == 3) buf = 0;
    }

    // ---------------- epilogue ----------------
    if (OUTM == 3) {
        __shared__ float srow[128];
        float* rs = const_cast<float*>(bias) + (size_t)b * NTOK;
        if (tid < 128) srow[tid] = 0.f;
        __syncthreads();
        bf16* C = (bf16*)Cout + (size_t)b * sC;
        #pragma unroll
        for (int mt = 0; mt < 4; mt++) {
            const int grow = M0 + wm * 64 + mt * 16 + g;
            float rp0 = 0.f, rp1 = 0.f;
            #pragma unroll
            for (int nt = 0; nt < 4; nt++) {
                const int gcol = N0 + wn * 32 + nt * 8 + tc;
                float e0 = __expf(acc[mt][nt][0]);
                float e1 = __expf(acc[mt][nt][1]);
                float e2 = __expf(acc[mt][nt][2]);
                float e3 = __expf(acc[mt][nt][3]);
                *(__nv_bfloat162*)(C + (size_t)grow * ldc + gcol) = __floats2bfloat162_rn(e0, e1);
                *(__nv_bfloat162*)(C + (size_t)(grow + 8) * ldc + gcol) = __floats2bfloat162_rn(e2, e3);
                rp0 += e0 + e1;
                rp1 += e2 + e3;
            }
            rp0 += __shfl_xor_sync(0xFFFFFFFFu, rp0, 1);
            rp0 += __shfl_xor_sync(0xFFFFFFFFu, rp0, 2);
            rp1 += __shfl_xor_sync(0xFFFFFFFFu, rp1, 1);
            rp1 += __shfl_xor_sync(0xFFFFFFFFu, rp1, 2);
            if ((lid & 3) == 0) {
                atomicAdd(&srow[wm * 64 + mt * 16 + g], rp0);
                atomicAdd(&srow[wm * 64 + mt * 16 + 8 + g], rp1);
            }
        }
        __syncthreads();
        if (tid < 128) atomicAdd(rs + M0 + tid, srow[tid]);
        return;
    }

    const float gm = (OUTM == 4) ? gamma[0] : 0.f;
    #pragma unroll
    for (int mt = 0; mt < 4; mt++) {
        #pragma unroll
        for (int nt = 0; nt < 4; nt++) {
            const int grow = M0 + wm * 64 + mt * 16 + g;
            const int gcol = N0 + wn * 32 + nt * 8 + tc;
            float d0 = acc[mt][nt][0], d1 = acc[mt][nt][1];
            float d2 = acc[mt][nt][2], d3 = acc[mt][nt][3];

            if (OUTM == 0) {
                float* C = (float*)Cout + (size_t)b * sC;
                if (BIASM == 1) {
                    float br0 = __ldg(bias + grow), br1 = __ldg(bias + grow + 8);
                    d0 += br0; d1 += br0; d2 += br1; d3 += br1;
                } else if (BIASM == 2) {
                    float bc0 = __ldg(bias + gcol), bc1 = __ldg(bias + gcol + 1);
                    d0 += bc0; d1 += bc1; d2 += bc0; d3 += bc1;
                }
                *(float2*)(C + (size_t)grow * ldc + gcol) = make_float2(d0, d1);
                *(float2*)(C + (size_t)(grow + 8) * ldc + gcol) = make_float2(d2, d3);
            } else if (OUTM == 1) {
                bf16* C = (bf16*)Cout + (size_t)b * sC;
                if (BIASM == 1) {
                    float br0 = __ldg(bias + grow), br1 = __ldg(bias + grow + 8);
                    d0 += br0; d1 += br0; d2 += br1; d3 += br1;
                } else if (BIASM == 2) {
                    float bc0 = __ldg(bias + gcol), bc1 = __ldg(bias + gcol + 1);
                    d0 += bc0; d1 += bc1; d2 += bc0; d3 += bc1;
                }
                *(__nv_bfloat162*)(C + (size_t)grow * ldc + gcol) = __floats2bfloat162_rn(d0, d1);
                *(__nv_bfloat162*)(C + (size_t)(grow + 8) * ldc + gcol) = __floats2bfloat162_rn(d2, d3);
            } else { // OUTM == 4
                const float* rs = bias + (size_t)b * NTOK;
                const float s0 = gm / __ldg(rs + gcol);
                const float s1 = gm / __ldg(rs + gcol + 1);
                float* C = (float*)Cout + (size_t)b * sC;
                float2 c0 = *(float2*)(C + (size_t)grow * ldc + gcol);
                float2 c1 = *(float2*)(C + (size_t)(grow + 8) * ldc + gcol);
                c0.x += s0 * d0; c0.y += s1 * d1;
                c1.x += s0 * d2; c1.y += s1 * d3;
                *(float2*)(C + (size_t)grow * ldc + gcol) = c0;
                *(float2*)(C + (size_t)(grow + 8) * ldc + gcol) = c1;
            }
        }
    }
}

// transpose fp32 [b][C][1024] -> bf16 hi(/lo) [b][1024][C]
__global__ __launch_bounds__(256) void transpose_split(
    const float* __restrict__ in, bf16* __restrict__ hi, bf16* __restrict__ lo, int C)
{
    __shared__ float t[32][33];
    const int c0 = blockIdx.x * 32, n0 = blockIdx.y * 32, b = blockIdx.z;
    const float* pin = in + (size_t)b * C * NTOK;
    const int tx = threadIdx.x & 31, ty = threadIdx.x >> 5;
    #pragma unroll
    for (int i = 0; i < 4; i++)
        t[ty + i * 8][tx] = pin[(size_t)(c0 + ty + i * 8) * NTOK + n0 + tx];
    __syncthreads();
    #pragma unroll
    for (int i = 0; i < 4; i++) {
        float x = t[tx][ty + i * 8];
        bf16 h = __float2bfloat16(x);
        size_t o = (size_t)b * NTOK * C + (size_t)(n0 + ty + i * 8) * C + c0 + tx;
        hi[o] = h;
        if (lo) lo[o] = __float2bfloat16(x - __bfloat162float(h));
    }
}

__global__ __launch_bounds__(256) void transpose_wc(
    const float* __restrict__ Wc, bf16* __restrict__ WcT)
{
    __shared__ float t[32][33];
    const int c0 = blockIdx.x * 32, r0 = blockIdx.y * 32;
    const int tx = threadIdx.x & 31, ty = threadIdx.x >> 5;
    #pragma unroll
    for (int i = 0; i < 4; i++)
        t[ty + i * 8][tx] = Wc[(size_t)(r0 + ty + i * 8) * HIDC + c0 + tx];
    __syncthreads();
    #pragma unroll
    for (int i = 0; i < 4; i++)
        WcT[(size_t)(c0 + ty + i * 8) * HIDC + r0 + tx] = __float2bfloat16(t[tx][ty + i * 8]);
}

__global__ void cast_weights(
    const float* __restrict__ Wq, const float* __restrict__ Wk,
    const float* __restrict__ Wv, const float* __restrict__ Wc,
    const float* __restrict__ We,
    bf16* __restrict__ oq, bf16* __restrict__ ok, bf16* __restrict__ ov,
    bf16* __restrict__ ch, bf16* __restrict__ cl, bf16* __restrict__ oe)
{
    const int i = blockIdx.x * 256 + threadIdx.x;
    const int w = blockIdx.y;
    if (w == 4) {
        if (i < HIDC * CEFF) oe[i] = __float2bfloat16(We[i]);
        return;
    }
    if (i >= HIDC * HIDC) return;
    if (w == 0)      oq[i] = __float2bfloat16(Wq[i]);
    else if (w == 1) ok[i] = __float2bfloat16(Wk[i]);
    else if (w == 2) ov[i] = __float2bfloat16(Wv[i]);
    else {
        float x = Wc[i];
        bf16 h = __float2bfloat16(x);
        ch[i] = h;
        cl[i] = __float2bfloat16(x - __bfloat162float(h));
    }
}

__global__ void combine_qbias(
    const float* __restrict__ Wq, const float* __restrict__ bcnn,
    const float* __restrict__ bq, float* __restrict__ bqc)
{
    const int o = blockIdx.x * 8 + (threadIdx.x >> 5);
    const int l = threadIdx.x & 31;
    float s = 0.f;
    for (int c = l; c < HIDC; c += 32) s += Wq[(size_t)o * HIDC + c] * bcnn[c];
    #pragma unroll
    for (int d = 16; d; d >>= 1) s += __shfl_xor_sync(0xFFFFFFFFu, s, d);
    if (l == 0) bqc[o] = s + bq[o];
}

// ------------------------------ launch ------------------------------------
extern "C" void kernel_launch(void* const* d_in, const int* in_sizes, int n_in,
                              void* d_out, int out_size)
{
    const float* xc = (const float*)d_in[0];
    const float* xe = (const float*)d_in[1];
    const float* Wc = (const float*)d_in[2];
    const float* bc = (const float*)d_in[3];
    const float* We = (const float*)d_in[4];
    const float* be = (const float*)d_in[5];
    const float* Wq = (const float*)d_in[6];
    const float* bq = (const float*)d_in[7];
    const float* Wk = (const float*)d_in[8];
    const float* bk = (const float*)d_in[9];
    const float* Wv = (const float*)d_in[10];
    const float* bv = (const float*)d_in[11];
    const float* gamma = (const float*)d_in[12];
    float* out = (float*)d_out;

    float *p_bqc, *p_rsum;
    bf16 *p_Wq_h, *p_Wk_h, *p_Wv_h, *p_We_h, *p_WcT, *p_Wc_h, *p_Wc_l, *p_Wqc_h;
    bf16 *p_XcT_h, *p_XcT_l, *p_XeT_h, *p_eff, *p_qb, *p_kb, *p_vb, *p_P;
    cudaGetSymbolAddress((void**)&p_bqc, g_bqc);
    cudaGetSymbolAddress((void**)&p_rsum, g_rsum);
    cudaGetSymbolAddress((void**)&p_Wq_h, g_Wq_h);
    cudaGetSymbolAddress((void**)&p_Wk_h, g_Wk_h);
    cudaGetSymbolAddress((void**)&p_Wv_h, g_Wv_h);
    cudaGetSymbolAddress((void**)&p_We_h, g_We_h);
    cudaGetSymbolAddress((void**)&p_WcT, g_WcT);
    cudaGetSymbolAddress((void**)&p_Wc_h, g_Wc_h);
    cudaGetSymbolAddress((void**)&p_Wc_l, g_Wc_l);
    cudaGetSymbolAddress((void**)&p_Wqc_h, g_Wqc_h);
    cudaGetSymbolAddress((void**)&p_XcT_h, g_XcT_h);
    cudaGetSymbolAddress((void**)&p_XcT_l, g_XcT_l);
    cudaGetSymbolAddress((void**)&p_XeT_h, g_XeT_h);
    cudaGetSymbolAddress((void**)&p_eff, g_eff);
    cudaGetSymbolAddress((void**)&p_qb, g_qb);
    cudaGetSymbolAddress((void**)&p_kb, g_kb);
    cudaGetSymbolAddress((void**)&p_vb, g_vb);
    cudaGetSymbolAddress((void**)&p_P, g_P);

    // lazily-created side stream + events (created on first, uncaptured call;
    // only record/wait appear inside graph capture)
    static cudaStream_t s1 = nullptr;
    static cudaEvent_t e_cast = nullptr, e_k = nullptr, e_v = nullptr;
    if (!s1) {
        cudaStreamCreateWithFlags(&s1, cudaStreamNonBlocking);
        cudaEventCreateWithFlags(&e_cast, cudaEventDisableTiming);
        cudaEventCreateWithFlags(&e_k, cudaEventDisableTiming);
        cudaEventCreateWithFlags(&e_v, cudaEventDisableTiming);
    }
    cudaStream_t s0 = 0;  // legacy default stream (capture stream)

    const int SM_PLAIN = 3 * 2 * TILEB;   // 110592
    const int SM_SPLIT = 3 * 4 * TILEB;   // 221184
    cudaFuncSetAttribute(mma_gemm<true, 1, 0>, cudaFuncAttributeMaxDynamicSharedMemorySize, SM_SPLIT);
    cudaFuncSetAttribute(mma_gemm<false, 0, 1>, cudaFuncAttributeMaxDynamicSharedMemorySize, SM_PLAIN);
    cudaFuncSetAttribute(mma_gemm<false, 2, 1>, cudaFuncAttributeMaxDynamicSharedMemorySize, SM_PLAIN);
    cudaFuncSetAttribute(mma_gemm<false, 1, 1>, cudaFuncAttributeMaxDynamicSharedMemorySize, SM_PLAIN);
    cudaFuncSetAttribute(mma_gemm<false, 0, 3>, cudaFuncAttributeMaxDynamicSharedMemorySize, SM_PLAIN);
    cudaFuncSetAttribute(mma_gemm<false, 0, 4>, cudaFuncAttributeMaxDynamicSharedMemorySize, SM_PLAIN);

    const size_t sXc = (size_t)NTOK * HIDC;
    const size_t sXe = (size_t)NTOK * CEFF;
    const size_t sO  = (size_t)HIDC * NTOK;
    const size_t sAt = (size_t)NTOK * NTOK;

    // ---- s0: shared prep ----
    cast_weights<<<dim3(2560, 5), 256, 0, s0>>>(Wq, Wk, Wv, Wc, We,
        p_Wq_h, p_Wk_h, p_Wv_h, p_Wc_h, p_Wc_l, p_We_h);
    cudaEventRecord(e_cast, s0);

    // ---- fork: s1 runs the efficient-features chain ----
    cudaStreamWaitEvent(s1, e_cast, 0);
    transpose_split<<<dim3(40, 32, BATCH), 256, 0, s1>>>(xe, p_XeT_h, nullptr, CEFF);
    mma_gemm<false, 2, 1><<<dim3(4, 8, BATCH), 256, SM_PLAIN, s1>>>(
        p_XeT_h, nullptr, p_We_h, nullptr, CEFF, CEFF, sXe, 0,
        p_eff, HIDC, sXc, be, nullptr, CEFF);
    mma_gemm<false, 2, 1><<<dim3(4, 8, BATCH), 256, SM_PLAIN, s1>>>(
        p_eff, nullptr, p_Wk_h, nullptr, HIDC, HIDC, sXc, 0,
        p_kb, HIDC, sXc, bk, nullptr, HIDC);
    cudaEventRecord(e_k, s1);
    mma_gemm<false, 1, 1><<<dim3(8, 4, BATCH), 256, SM_PLAIN, s1>>>(
        p_Wv_h, nullptr, p_eff, nullptr, HIDC, HIDC, 0, sXc,
        p_vb, NTOK, sO, bv, nullptr, HIDC);
    cudaEventRecord(e_v, s1);

    // ---- s0: cnn-features chain ----
    transpose_wc<<<dim3(16, 16), 256, 0, s0>>>(Wc, p_WcT);
    combine_qbias<<<64, 256, 0, s0>>>(Wq, bc, bq, p_bqc);
    cudaMemsetAsync(p_rsum, 0, (size_t)BATCH * NTOK * sizeof(float), s0);
    mma_gemm<false, 0, 1><<<dim3(4, 4, 1), 256, SM_PLAIN, s0>>>(
        p_Wq_h, nullptr, p_WcT, nullptr, HIDC, HIDC, 0, 0,
        p_Wqc_h, HIDC, 0, nullptr, nullptr, HIDC);
    transpose_split<<<dim3(16, 32, BATCH), 256, 0, s0>>>(xc, p_XcT_h, p_XcT_l, HIDC);
    mma_gemm<true, 1, 0><<<dim3(8, 4, BATCH), 256, SM_SPLIT, s0>>>(
        p_Wc_h, p_Wc_l, p_XcT_h, p_XcT_l, HIDC, HIDC, 0, sXc,
        out, NTOK, sO, bc, nullptr, HIDC);
    mma_gemm<false, 2, 1><<<dim3(4, 8, BATCH), 256, SM_PLAIN, s0>>>(
        p_XcT_h, nullptr, p_Wqc_h, nullptr, HIDC, HIDC, sXc, 0,
        p_qb, HIDC, sXc, p_bqc, nullptr, HIDC);

    // ---- join for logits (needs q on s0, k on s1) ----
    cudaStreamWaitEvent(s0, e_k, 0);
    mma_gemm<false, 0, 3><<<dim3(8, 8, BATCH), 256, SM_PLAIN, s0>>>(
        p_qb, nullptr, p_kb, nullptr, HIDC, HIDC, sXc, sXc,
        p_P, NTOK, sAt, p_rsum, nullptr, HIDC);

    // ---- join for PV (needs v on s1; cnn + logits already on s0) ----
    cudaStreamWaitEvent(s0, e_v, 0);
    mma_gemm<false, 0, 4><<<dim3(8, 4, BATCH), 256, SM_PLAIN, s0>>>(
        p_vb, nullptr, p_P, nullptr, NTOK, NTOK, sO, sAt,
        out, NTOK, sO, p_rsum, gamma, NTOK);
}

// round 13
// speedup vs baseline: 1.2981x; 1.1440x over previous
#include <cuda_runtime.h>
#include <cuda_fp16.h>
#include <cstdint>
#include <cstddef>

#define HIDC 512
#define NTOK 1024
#define BATCH 32
#define CEFF 1280

typedef __half h16;

// ------------------------- scratch ---------------------------------------
__device__ float g_bqc[HIDC];
__device__ float g_rsum[(size_t)BATCH * NTOK];

__device__ h16 g_Wq_h[HIDC * HIDC], g_Wk_h[HIDC * HIDC], g_Wv_h[HIDC * HIDC];
__device__ h16 g_We_h[HIDC * CEFF];
__device__ h16 g_WcT[HIDC * HIDC];
__device__ h16 g_Wc_h[HIDC * HIDC];
__device__ h16 g_Wqc_h[HIDC * HIDC];

__device__ h16 g_XcT[(size_t)BATCH * NTOK * HIDC];
__device__ h16 g_XeT[(size_t)BATCH * NTOK * CEFF];

__device__ h16 g_eff[(size_t)BATCH * NTOK * HIDC];
__device__ h16 g_qb[(size_t)BATCH * NTOK * HIDC];
__device__ h16 g_kb[(size_t)BATCH * NTOK * HIDC];
__device__ h16 g_vb[(size_t)BATCH * HIDC * NTOK];
__device__ h16 g_P[(size_t)BATCH * NTOK * NTOK];

#define MMA_F16(D, A_, B_) \
    asm volatile("mma.sync.aligned.m16n8k16.row.col.f32.f16.f16.f32 " \
        "{%0,%1,%2,%3}, {%4,%5,%6,%7}, {%8,%9}, {%0,%1,%2,%3};" \
        : "+f"((D)[0]), "+f"((D)[1]), "+f"((D)[2]), "+f"((D)[3]) \
        : "r"((A_)[0]), "r"((A_)[1]), "r"((A_)[2]), "r"((A_)[3]), \
          "r"((B_)[0]), "r"((B_)[1]))

#define LDSM4(R0, R1, R2, R3, ADDR) \
    asm volatile("ldmatrix.sync.aligned.m8n8.x4.shared.b16 {%0,%1,%2,%3}, [%4];" \
        : "=r"(R0), "=r"(R1), "=r"(R2), "=r"(R3) : "r"(ADDR))

__device__ __forceinline__ uint32_t smem_u32(const void* p) {
    uint32_t a;
    asm("{ .reg .u64 t; cvta.to.shared.u64 t, %1; cvt.u32.u64 %0, t; }" : "=r"(a) : "l"(p));
    return a;
}
__device__ __forceinline__ void cp16(uint32_t dst, const void* src) {
    asm volatile("cp.async.cg.shared.global [%0], [%1], 16;" :: "r"(dst), "l"(src));
}
__device__ __forceinline__ void cp_commit() {
    asm volatile("cp.async.commit_group;" ::: "memory");
}
template<int N> __device__ __forceinline__ void cp_wait() {
    asm volatile("cp.async.wait_group %0;" :: "n"(N) : "memory");
}

#define TILEB 18432   // 128 rows * 72 elems * 2B

// ---------------------------------------------------------------------------
// fp16 HMMA GEMM, 3-stage cp.async pipeline, BK=64, ldmatrix fragments.
// C[M0+128, N0+128] = sum_K A[m,k] * B[n,k]  (both K-major)
// BIASM: 0 none, 1 bias[row], 2 bias[col]
// OUTM: 0 fp32 row-major (+bias) | 1 fp16 row-major (+bias)
//       3 fp16 exp(D) + rowsum atomics | 4 fp32 RMW += gamma/rowsum[col]*D
// ---------------------------------------------------------------------------
template<int BIASM, int OUTM>
__global__ __launch_bounds__(256) void mma_gemm(
    const h16* __restrict__ A, const h16* __restrict__ B,
    int lda, int ldb, size_t sA, size_t sB,
    void* __restrict__ Cout, int ldc, size_t sC,
    const float* __restrict__ bias, const float* __restrict__ gamma, int K)
{
    extern __shared__ char dynsm[];
    constexpr int STAGE = 2 * TILEB;
    const uint32_t sm0 = smem_u32(dynsm);

    const int tid = threadIdx.x;
    const int wid = tid >> 5;
    const int lid = tid & 31;
    const int wm = wid & 1;
    const int wn = wid >> 1;
    const int g  = lid >> 2;
    const int tc = (lid & 3) * 2;

    const int M0 = blockIdx.y * 128;
    const int N0 = blockIdx.x * 128;
    const int b  = blockIdx.z;

    const h16* pA = A + (size_t)b * sA + (size_t)M0 * lda;
    const h16* pB = B + (size_t)b * sB + (size_t)N0 * ldb;

    const int l8  = lid & 7;
    const int mi1 = (lid >> 3) & 1;
    const int mi2 = (lid >> 4) & 1;
    const uint32_t offA = (uint32_t)(((wm * 64 + mi1 * 8 + l8) * 72 + mi2 * 8) * 2);
    const uint32_t offB = (uint32_t)(((wn * 32 + mi2 * 8 + l8) * 72 + mi1 * 8) * 2);

    float acc[4][4][4];
    #pragma unroll
    for (int i = 0; i < 4; i++)
        #pragma unroll
        for (int j = 0; j < 4; j++)
            #pragma unroll
            for (int r = 0; r < 4; r++) acc[i][j][r] = 0.f;

    const int nk = K >> 6;

    auto copy_stage = [&](int buf, int kt) {
        const int k0 = kt << 6;
        const uint32_t sb = sm0 + buf * STAGE;
        #pragma unroll
        for (int s = 0; s < 4; s++) {
            const int i = tid + s * 256;
            const int r = i >> 3, c = (i & 7) * 8;
            const uint32_t so = (uint32_t)((r * 72 + c) * 2);
            cp16(sb + so,         pA + (size_t)r * lda + k0 + c);
            cp16(sb + TILEB + so, pB + (size_t)r * ldb + k0 + c);
        }
        cp_commit();
    };

    copy_stage(0, 0);
    copy_stage(1, 1);

    int buf = 0;
    for (int kt = 0; kt < nk; kt++) {
        if (kt + 2 < nk) {
            int nb = buf + 2; if (nb >= 3) nb -= 3;
            copy_stage(nb, kt + 2);
            cp_wait<2>();
        } else if (kt + 1 < nk) {
            cp_wait<1>();
        } else {
            cp_wait<0>();
        }
        __syncthreads();

        const uint32_t sb = sm0 + buf * STAGE;
        #pragma unroll
        for (int ks = 0; ks < 64; ks += 16) {
            uint32_t a[4][4], bb[4][2];
            #pragma unroll
            for (int mt = 0; mt < 4; mt++)
                LDSM4(a[mt][0], a[mt][1], a[mt][2], a[mt][3],
                      sb + offA + mt * 2304 + ks * 2);
            #pragma unroll
            for (int p = 0; p < 2; p++)
                LDSM4(bb[2 * p][0], bb[2 * p][1], bb[2 * p + 1][0], bb[2 * p + 1][1],
                      sb + TILEB + offB + p * 2304 + ks * 2);
            #pragma unroll
            for (int mt = 0; mt < 4; mt++)
                #pragma unroll
                for (int nt = 0; nt < 4; nt++)
                    MMA_F16(acc[mt][nt], a[mt], bb[nt]);
        }
        __syncthreads();
        if (++buf == 3) buf = 0;
    }

    // ---------------- epilogue ----------------
    if (OUTM == 3) {
        __shared__ float srow[128];
        float* rs = const_cast<float*>(bias) + (size_t)b * NTOK;
        if (tid < 128) srow[tid] = 0.f;
        __syncthreads();
        h16* C = (h16*)Cout + (size_t)b * sC;
        #pragma unroll
        for (int mt = 0; mt < 4; mt++) {
            const int grow = M0 + wm * 64 + mt * 16 + g;
            float rp0 = 0.f, rp1 = 0.f;
            #pragma unroll
            for (int nt = 0; nt < 4; nt++) {
                const int gcol = N0 + wn * 32 + nt * 8 + tc;
                float e0 = __expf(acc[mt][nt][0]);
                float e1 = __expf(acc[mt][nt][1]);
                float e2 = __expf(acc[mt][nt][2]);
                float e3 = __expf(acc[mt][nt][3]);
                *(__half2*)(C + (size_t)grow * ldc + gcol) = __floats2half2_rn(e0, e1);
                *(__half2*)(C + (size_t)(grow + 8) * ldc + gcol) = __floats2half2_rn(e2, e3);
                rp0 += e0 + e1;
                rp1 += e2 + e3;
            }
            rp0 += __shfl_xor_sync(0xFFFFFFFFu, rp0, 1);
            rp0 += __shfl_xor_sync(0xFFFFFFFFu, rp0, 2);
            rp1 += __shfl_xor_sync(0xFFFFFFFFu, rp1, 1);
            rp1 += __shfl_xor_sync(0xFFFFFFFFu, rp1, 2);
            if ((lid & 3) == 0) {
                atomicAdd(&srow[wm * 64 + mt * 16 + g], rp0);
                atomicAdd(&srow[wm * 64 + mt * 16 + 8 + g], rp1);
            }
        }
        __syncthreads();
        if (tid < 128) atomicAdd(rs + M0 + tid, srow[tid]);
        return;
    }

    const float gm = (OUTM == 4) ? gamma[0] : 0.f;
    #pragma unroll
    for (int mt = 0; mt < 4; mt++) {
        #pragma unroll
        for (int nt = 0; nt < 4; nt++) {
            const int grow = M0 + wm * 64 + mt * 16 + g;
            const int gcol = N0 + wn * 32 + nt * 8 + tc;
            float d0 = acc[mt][nt][0], d1 = acc[mt][nt][1];
            float d2 = acc[mt][nt][2], d3 = acc[mt][nt][3];

            if (OUTM == 0 || OUTM == 1) {
                if (BIASM == 1) {
                    float br0 = __ldg(bias + grow), br1 = __ldg(bias + grow + 8);
                    d0 += br0; d1 += br0; d2 += br1; d3 += br1;
                } else if (BIASM == 2) {
                    float bc0 = __ldg(bias + gcol), bc1 = __ldg(bias + gcol + 1);
                    d0 += bc0; d1 += bc1; d2 += bc0; d3 += bc1;
                }
            }

            if (OUTM == 0) {
                float* C = (float*)Cout + (size_t)b * sC;
                *(float2*)(C + (size_t)grow * ldc + gcol) = make_float2(d0, d1);
                *(float2*)(C + (size_t)(grow + 8) * ldc + gcol) = make_float2(d2, d3);
            } else if (OUTM == 1) {
                h16* C = (h16*)Cout + (size_t)b * sC;
                *(__half2*)(C + (size_t)grow * ldc + gcol) = __floats2half2_rn(d0, d1);
                *(__half2*)(C + (size_t)(grow + 8) * ldc + gcol) = __floats2half2_rn(d2, d3);
            } else { // OUTM == 4
                const float* rs = bias + (size_t)b * NTOK;
                const float s0 = gm / __ldg(rs + gcol);
                const float s1 = gm / __ldg(rs + gcol + 1);
                float* C = (float*)Cout + (size_t)b * sC;
                float2 c0 = *(float2*)(C + (size_t)grow * ldc + gcol);
                float2 c1 = *(float2*)(C + (size_t)(grow + 8) * ldc + gcol);
                c0.x += s0 * d0; c0.y += s1 * d1;
                c1.x += s0 * d2; c1.y += s1 * d3;
                *(float2*)(C + (size_t)grow * ldc + gcol) = c0;
                *(float2*)(C + (size_t)(grow + 8) * ldc + gcol) = c1;
            }
        }
    }
}

// transpose fp32 [b][C][1024] -> fp16 [b][1024][C]
__global__ __launch_bounds__(256) void transpose_h(
    const float* __restrict__ in, h16* __restrict__ outp, int C)
{
    __shared__ float t[32][33];
    const int c0 = blockIdx.x * 32, n0 = blockIdx.y * 32, b = blockIdx.z;
    const float* pin = in + (size_t)b * C * NTOK;
    const int tx = threadIdx.x & 31, ty = threadIdx.x >> 5;
    #pragma unroll
    for (int i = 0; i < 4; i++)
        t[ty + i * 8][tx] = pin[(size_t)(c0 + ty + i * 8) * NTOK + n0 + tx];
    __syncthreads();
    #pragma unroll
    for (int i = 0; i < 4; i++) {
        size_t o = (size_t)b * NTOK * C + (size_t)(n0 + ty + i * 8) * C + c0 + tx;
        outp[o] = __float2half_rn(t[tx][ty + i * 8]);
    }
}

__global__ __launch_bounds__(256) void transpose_wc(
    const float* __restrict__ Wc, h16* __restrict__ WcT)
{
    __shared__ float t[32][33];
    const int c0 = blockIdx.x * 32, r0 = blockIdx.y * 32;
    const int tx = threadIdx.x & 31, ty = threadIdx.x >> 5;
    #pragma unroll
    for (int i = 0; i < 4; i++)
        t[ty + i * 8][tx] = Wc[(size_t)(r0 + ty + i * 8) * HIDC + c0 + tx];
    __syncthreads();
    #pragma unroll
    for (int i = 0; i < 4; i++)
        WcT[(size_t)(c0 + ty + i * 8) * HIDC + r0 + tx] = __float2half_rn(t[tx][ty + i * 8]);
}

// fused weight casts: y=0 Wq, y=1 Wk, y=2 Wv, y=3 Wc, y=4 We
__global__ void cast_weights(
    const float* __restrict__ Wq, const float* __restrict__ Wk,
    const float* __restrict__ Wv, const float* __restrict__ Wc,
    const float* __restrict__ We,
    h16* __restrict__ oq, h16* __restrict__ ok, h16* __restrict__ ov,
    h16* __restrict__ oc, h16* __restrict__ oe)
{
    const int i = blockIdx.x * 256 + threadIdx.x;
    const int w = blockIdx.y;
    if (w == 4) {
        if (i < HIDC * CEFF) oe[i] = __float2half_rn(We[i]);
        return;
    }
    if (i >= HIDC * HIDC) return;
    if (w == 0)      oq[i] = __float2half_rn(Wq[i]);
    else if (w == 1) ok[i] = __float2half_rn(Wk[i]);
    else if (w == 2) ov[i] = __float2half_rn(Wv[i]);
    else             oc[i] = __float2half_rn(Wc[i]);
}

__global__ void combine_qbias(
    const float* __restrict__ Wq, const float* __restrict__ bcnn,
    const float* __restrict__ bq, float* __restrict__ bqc)
{
    const int o = blockIdx.x * 8 + (threadIdx.x >> 5);
    const int l = threadIdx.x & 31;
    float s = 0.f;
    for (int c = l; c < HIDC; c += 32) s += Wq[(size_t)o * HIDC + c] * bcnn[c];
    #pragma unroll
    for (int d = 16; d; d >>= 1) s += __shfl_xor_sync(0xFFFFFFFFu, s, d);
    if (l == 0) bqc[o] = s + bq[o];
}

// ------------------------------ launch ------------------------------------
extern "C" void kernel_launch(void* const* d_in, const int* in_sizes, int n_in,
                              void* d_out, int out_size)
{
    const float* xc = (const float*)d_in[0];
    const float* xe = (const float*)d_in[1];
    const float* Wc = (const float*)d_in[2];
    const float* bc = (const float*)d_in[3];
    const float* We = (const float*)d_in[4];
    const float* be = (const float*)d_in[5];
    const float* Wq = (const float*)d_in[6];
    const float* bq = (const float*)d_in[7];
    const float* Wk = (const float*)d_in[8];
    const float* bk = (const float*)d_in[9];
    const float* Wv = (const float*)d_in[10];
    const float* bv = (const float*)d_in[11];
    const float* gamma = (const float*)d_in[12];
    float* out = (float*)d_out;

    float *p_bqc, *p_rsum;
    h16 *p_Wq_h, *p_Wk_h, *p_Wv_h, *p_We_h, *p_WcT, *p_Wc_h, *p_Wqc_h;
    h16 *p_XcT, *p_XeT, *p_eff, *p_qb, *p_kb, *p_vb, *p_P;
    cudaGetSymbolAddress((void**)&p_bqc, g_bqc);
    cudaGetSymbolAddress((void**)&p_rsum, g_rsum);
    cudaGetSymbolAddress((void**)&p_Wq_h, g_Wq_h);
    cudaGetSymbolAddress((void**)&p_Wk_h, g_Wk_h);
    cudaGetSymbolAddress((void**)&p_Wv_h, g_Wv_h);
    cudaGetSymbolAddress((void**)&p_We_h, g_We_h);
    cudaGetSymbolAddress((void**)&p_WcT, g_WcT);
    cudaGetSymbolAddress((void**)&p_Wc_h, g_Wc_h);
    cudaGetSymbolAddress((void**)&p_Wqc_h, g_Wqc_h);
    cudaGetSymbolAddress((void**)&p_XcT, g_XcT);
    cudaGetSymbolAddress((void**)&p_XeT, g_XeT);
    cudaGetSymbolAddress((void**)&p_eff, g_eff);
    cudaGetSymbolAddress((void**)&p_qb, g_qb);
    cudaGetSymbolAddress((void**)&p_kb, g_kb);
    cudaGetSymbolAddress((void**)&p_vb, g_vb);
    cudaGetSymbolAddress((void**)&p_P, g_P);

    static cudaStream_t s1 = nullptr;
    static cudaEvent_t e_cast = nullptr, e_eff = nullptr, e_v = nullptr;
    if (!s1) {
        cudaStreamCreateWithFlags(&s1, cudaStreamNonBlocking);
        cudaEventCreateWithFlags(&e_cast, cudaEventDisableTiming);
        cudaEventCreateWithFlags(&e_eff, cudaEventDisableTiming);
        cudaEventCreateWithFlags(&e_v, cudaEventDisableTiming);
    }
    cudaStream_t s0 = 0;

    const int SM_PLAIN = 3 * 2 * TILEB;   // 110592
    cudaFuncSetAttribute(mma_gemm<1, 0>, cudaFuncAttributeMaxDynamicSharedMemorySize, SM_PLAIN);
    cudaFuncSetAttribute(mma_gemm<0, 1>, cudaFuncAttributeMaxDynamicSharedMemorySize, SM_PLAIN);
    cudaFuncSetAttribute(mma_gemm<2, 1>, cudaFuncAttributeMaxDynamicSharedMemorySize, SM_PLAIN);
    cudaFuncSetAttribute(mma_gemm<1, 1>, cudaFuncAttributeMaxDynamicSharedMemorySize, SM_PLAIN);
    cudaFuncSetAttribute(mma_gemm<0, 3>, cudaFuncAttributeMaxDynamicSharedMemorySize, SM_PLAIN);
    cudaFuncSetAttribute(mma_gemm<0, 4>, cudaFuncAttributeMaxDynamicSharedMemorySize, SM_PLAIN);

    const size_t sXc = (size_t)NTOK * HIDC;
    const size_t sXe = (size_t)NTOK * CEFF;
    const size_t sO  = (size_t)HIDC * NTOK;
    const size_t sAt = (size_t)NTOK * NTOK;

    // ---- s0: shared prep ----
    cast_weights<<<dim3(2560, 5), 256, 0, s0>>>(Wq, Wk, Wv, Wc, We,
        p_Wq_h, p_Wk_h, p_Wv_h, p_Wc_h, p_We_h);
    cudaEventRecord(e_cast, s0);

    // ---- s1: efficient chain (heavy eff GEMM) ----
    cudaStreamWaitEvent(s1, e_cast, 0);
    transpose_h<<<dim3(40, 32, BATCH), 256, 0, s1>>>(xe, p_XeT, CEFF);
    mma_gemm<2, 1><<<dim3(4, 8, BATCH), 256, SM_PLAIN, s1>>>(
        p_XeT, p_We_h, CEFF, CEFF, sXe, 0, p_eff, HIDC, sXc, be, nullptr, CEFF);
    cudaEventRecord(e_eff, s1);
    mma_gemm<1, 1><<<dim3(8, 4, BATCH), 256, SM_PLAIN, s1>>>(
        p_Wv_h, p_eff, HIDC, HIDC, 0, sXc, p_vb, NTOK, sO, bv, nullptr, HIDC);
    cudaEventRecord(e_v, s1);

    // ---- s0: cnn chain ----
    transpose_wc<<<dim3(16, 16), 256, 0, s0>>>(Wc, p_WcT);
    combine_qbias<<<64, 256, 0, s0>>>(Wq, bc, bq, p_bqc);
    cudaMemsetAsync(p_rsum, 0, (size_t)BATCH * NTOK * sizeof(float), s0);
    mma_gemm<0, 1><<<dim3(4, 4, 1), 256, SM_PLAIN, s0>>>(
        p_Wq_h, p_WcT, HIDC, HIDC, 0, 0, p_Wqc_h, HIDC, 0, nullptr, nullptr, HIDC);
    transpose_h<<<dim3(16, 32, BATCH), 256, 0, s0>>>(xc, p_XcT, HIDC);
    // cnn_proj single-pass fp16 -> d_out fp32 [b][c][n]
    mma_gemm<1, 0><<<dim3(8, 4, BATCH), 256, SM_PLAIN, s0>>>(
        p_Wc_h, p_XcT, HIDC, HIDC, 0, sXc, out, NTOK, sO, bc, nullptr, HIDC);
    // q
    mma_gemm<2, 1><<<dim3(4, 8, BATCH), 256, SM_PLAIN, s0>>>(
        p_XcT, p_Wqc_h, HIDC, HIDC, sXc, 0, p_qb, HIDC, sXc, p_bqc, nullptr, HIDC);

    // k on s0 after eff ready (balance: v stays on s1)
    cudaStreamWaitEvent(s0, e_eff, 0);
    mma_gemm<2, 1><<<dim3(4, 8, BATCH), 256, SM_PLAIN, s0>>>(
        p_eff, p_Wk_h, HIDC, HIDC, sXc, 0, p_kb, HIDC, sXc, bk, nullptr, HIDC);

    // fused logits + exp + rowsum -> P
    mma_gemm<0, 3><<<dim3(8, 8, BATCH), 256, SM_PLAIN, s0>>>(
        p_qb, p_kb, HIDC, HIDC, sXc, sXc, p_P, NTOK, sAt, p_rsum, nullptr, HIDC);

    // PV after v ready
    cudaStreamWaitEvent(s0, e_v, 0);
    mma_gemm<0, 4><<<dim3(8, 4, BATCH), 256, SM_PLAIN, s0>>>(
        p_vb, p_P, NTOK, NTOK, sO, sAt, out, NTOK, sO, p_rsum, gamma, NTOK);
}

// round 14
// speedup vs baseline: 1.3988x; 1.0776x over previous
#include <cuda_runtime.h>
#include <cuda_fp16.h>
#include <cstdint>
#include <cstddef>

#define HIDC 512
#define NTOK 1024
#define BATCH 32
#define CEFF 1280

typedef __half h16;

// ------------------------- scratch ---------------------------------------
__device__ float g_bqc[HIDC], g_bq2[HIDC];
__device__ float g_rsum[(size_t)BATCH * NTOK];

__device__ h16 g_Wq_h[HIDC * HIDC], g_Wk_h[HIDC * HIDC], g_Wv_h[HIDC * HIDC];
__device__ h16 g_We_h[HIDC * CEFF];
__device__ h16 g_WcT[HIDC * HIDC];
__device__ h16 g_WkT[HIDC * HIDC];
__device__ h16 g_Wc_h[HIDC * HIDC];
__device__ h16 g_WqcT[HIDC * HIDC];   // Wqc^T = (Wq @ Wc)^T
__device__ h16 g_Wq2[HIDC * HIDC];    // Wq2[i][c] = sum_a Wk[a][i] Wqc[a][c]

__device__ h16 g_XcT[(size_t)BATCH * NTOK * HIDC];
__device__ h16 g_XeT[(size_t)BATCH * NTOK * CEFF];

__device__ h16 g_eff[(size_t)BATCH * NTOK * HIDC];
__device__ h16 g_qb[(size_t)BATCH * NTOK * HIDC];     // q2 [b][n][i]
__device__ h16 g_vb[(size_t)BATCH * HIDC * NTOK];
__device__ h16 g_P[(size_t)BATCH * NTOK * NTOK];

#define MMA_F16(D, A_, B_) \
    asm volatile("mma.sync.aligned.m16n8k16.row.col.f32.f16.f16.f32 " \
        "{%0,%1,%2,%3}, {%4,%5,%6,%7}, {%8,%9}, {%0,%1,%2,%3};" \
        : "+f"((D)[0]), "+f"((D)[1]), "+f"((D)[2]), "+f"((D)[3]) \
        : "r"((A_)[0]), "r"((A_)[1]), "r"((A_)[2]), "r"((A_)[3]), \
          "r"((B_)[0]), "r"((B_)[1]))

#define LDSM4(R0, R1, R2, R3, ADDR) \
    asm volatile("ldmatrix.sync.aligned.m8n8.x4.shared.b16 {%0,%1,%2,%3}, [%4];" \
        : "=r"(R0), "=r"(R1), "=r"(R2), "=r"(R3) : "r"(ADDR))

__device__ __forceinline__ uint32_t smem_u32(const void* p) {
    uint32_t a;
    asm("{ .reg .u64 t; cvta.to.shared.u64 t, %1; cvt.u32.u64 %0, t; }" : "=r"(a) : "l"(p));
    return a;
}
__device__ __forceinline__ void cp16(uint32_t dst, const void* src) {
    asm volatile("cp.async.cg.shared.global [%0], [%1], 16;" :: "r"(dst), "l"(src));
}
__device__ __forceinline__ void cp_commit() {
    asm volatile("cp.async.commit_group;" ::: "memory");
}
template<int N> __device__ __forceinline__ void cp_wait() {
    asm volatile("cp.async.wait_group %0;" :: "n"(N) : "memory");
}

#define TILEB 18432   // 128 rows * 72 elems * 2B

// ---------------------------------------------------------------------------
// fp16 HMMA GEMM, 3-stage cp.async pipeline, BK=64, ldmatrix fragments.
// C[M0+128, N0+128] = sum_K A[m,k] * B[n,k]  (both K-major)
// BIASM: 0 none, 1 bias[row], 2 bias[col]
// OUTM: 0 fp32 row-major (+bias) | 1 fp16 row-major (+bias)
//       3 fp16 exp(D) + rowsum atomics | 4 fp32 RMW += gamma/rowsum[col]*D
// ---------------------------------------------------------------------------
template<int BIASM, int OUTM>
__global__ __launch_bounds__(256) void mma_gemm(
    const h16* __restrict__ A, const h16* __restrict__ B,
    int lda, int ldb, size_t sA, size_t sB,
    void* __restrict__ Cout, int ldc, size_t sC,
    const float* __restrict__ bias, const float* __restrict__ gamma, int K)
{
    extern __shared__ char dynsm[];
    constexpr int STAGE = 2 * TILEB;
    const uint32_t sm0 = smem_u32(dynsm);

    const int tid = threadIdx.x;
    const int wid = tid >> 5;
    const int lid = tid & 31;
    const int wm = wid & 1;
    const int wn = wid >> 1;
    const int g  = lid >> 2;
    const int tc = (lid & 3) * 2;

    const int M0 = blockIdx.y * 128;
    const int N0 = blockIdx.x * 128;
    const int b  = blockIdx.z;

    const h16* pA = A + (size_t)b * sA + (size_t)M0 * lda;
    const h16* pB = B + (size_t)b * sB + (size_t)N0 * ldb;

    const int l8  = lid & 7;
    const int mi1 = (lid >> 3) & 1;
    const int mi2 = (lid >> 4) & 1;
    const uint32_t offA = (uint32_t)(((wm * 64 + mi1 * 8 + l8) * 72 + mi2 * 8) * 2);
    const uint32_t offB = (uint32_t)(((wn * 32 + mi2 * 8 + l8) * 72 + mi1 * 8) * 2);

    float acc[4][4][4];
    #pragma unroll
    for (int i = 0; i < 4; i++)
        #pragma unroll
        for (int j = 0; j < 4; j++)
            #pragma unroll
            for (int r = 0; r < 4; r++) acc[i][j][r] = 0.f;

    const int nk = K >> 6;

    auto copy_stage = [&](int buf, int kt) {
        const int k0 = kt << 6;
        const uint32_t sb = sm0 + buf * STAGE;
        #pragma unroll
        for (int s = 0; s < 4; s++) {
            const int i = tid + s * 256;
            const int r = i >> 3, c = (i & 7) * 8;
            const uint32_t so = (uint32_t)((r * 72 + c) * 2);
            cp16(sb + so,         pA + (size_t)r * lda + k0 + c);
            cp16(sb + TILEB + so, pB + (size_t)r * ldb + k0 + c);
        }
        cp_commit();
    };

    copy_stage(0, 0);
    copy_stage(1, 1);

    int buf = 0;
    for (int kt = 0; kt < nk; kt++) {
        if (kt + 2 < nk) {
            int nb = buf + 2; if (nb >= 3) nb -= 3;
            copy_stage(nb, kt + 2);
            cp_wait<2>();
        } else if (kt + 1 < nk) {
            cp_wait<1>();
        } else {
            cp_wait<0>();
        }
        __syncthreads();

        const uint32_t sb = sm0 + buf * STAGE;
        #pragma unroll
        for (int ks = 0; ks < 64; ks += 16) {
            uint32_t a[4][4], bb[4][2];
            #pragma unroll
            for (int mt = 0; mt < 4; mt++)
                LDSM4(a[mt][0], a[mt][1], a[mt][2], a[mt][3],
                      sb + offA + mt * 2304 + ks * 2);
            #pragma unroll
            for (int p = 0; p < 2; p++)
                LDSM4(bb[2 * p][0], bb[2 * p][1], bb[2 * p + 1][0], bb[2 * p + 1][1],
                      sb + TILEB + offB + p * 2304 + ks * 2);
            #pragma unroll
            for (int mt = 0; mt < 4; mt++)
                #pragma unroll
                for (int nt = 0; nt < 4; nt++)
                    MMA_F16(acc[mt][nt], a[mt], bb[nt]);
        }
        __syncthreads();
        if (++buf == 3) buf = 0;
    }

    // ---------------- epilogue ----------------
    if (OUTM == 3) {
        __shared__ float srow[128];
        float* rs = const_cast<float*>(bias) + (size_t)b * NTOK;
        if (tid < 128) srow[tid] = 0.f;
        __syncthreads();
        h16* C = (h16*)Cout + (size_t)b * sC;
        #pragma unroll
        for (int mt = 0; mt < 4; mt++) {
            const int grow = M0 + wm * 64 + mt * 16 + g;
            float rp0 = 0.f, rp1 = 0.f;
            #pragma unroll
            for (int nt = 0; nt < 4; nt++) {
                const int gcol = N0 + wn * 32 + nt * 8 + tc;
                float e0 = __expf(acc[mt][nt][0]);
                float e1 = __expf(acc[mt][nt][1]);
                float e2 = __expf(acc[mt][nt][2]);
                float e3 = __expf(acc[mt][nt][3]);
                *(__half2*)(C + (size_t)grow * ldc + gcol) = __floats2half2_rn(e0, e1);
                *(__half2*)(C + (size_t)(grow + 8) * ldc + gcol) = __floats2half2_rn(e2, e3);
                rp0 += e0 + e1;
                rp1 += e2 + e3;
            }
            rp0 += __shfl_xor_sync(0xFFFFFFFFu, rp0, 1);
            rp0 += __shfl_xor_sync(0xFFFFFFFFu, rp0, 2);
            rp1 += __shfl_xor_sync(0xFFFFFFFFu, rp1, 1);
            rp1 += __shfl_xor_sync(0xFFFFFFFFu, rp1, 2);
            if ((lid & 3) == 0) {
                atomicAdd(&srow[wm * 64 + mt * 16 + g], rp0);
                atomicAdd(&srow[wm * 64 + mt * 16 + 8 + g], rp1);
            }
        }
        __syncthreads();
        if (tid < 128) atomicAdd(rs + M0 + tid, srow[tid]);
        return;
    }

    const float gm = (OUTM == 4) ? gamma[0] : 0.f;
    #pragma unroll
    for (int mt = 0; mt < 4; mt++) {
        #pragma unroll
        for (int nt = 0; nt < 4; nt++) {
            const int grow = M0 + wm * 64 + mt * 16 + g;
            const int gcol = N0 + wn * 32 + nt * 8 + tc;
            float d0 = acc[mt][nt][0], d1 = acc[mt][nt][1];
            float d2 = acc[mt][nt][2], d3 = acc[mt][nt][3];

            if (OUTM == 0 || OUTM == 1) {
                if (BIASM == 1) {
                    float br0 = __ldg(bias + grow), br1 = __ldg(bias + grow + 8);
                    d0 += br0; d1 += br0; d2 += br1; d3 += br1;
                } else if (BIASM == 2) {
                    float bc0 = __ldg(bias + gcol), bc1 = __ldg(bias + gcol + 1);
                    d0 += bc0; d1 += bc1; d2 += bc0; d3 += bc1;
                }
            }

            if (OUTM == 0) {
                float* C = (float*)Cout + (size_t)b * sC;
                *(float2*)(C + (size_t)grow * ldc + gcol) = make_float2(d0, d1);
                *(float2*)(C + (size_t)(grow + 8) * ldc + gcol) = make_float2(d2, d3);
            } else if (OUTM == 1) {
                h16* C = (h16*)Cout + (size_t)b * sC;
                *(__half2*)(C + (size_t)grow * ldc + gcol) = __floats2half2_rn(d0, d1);
                *(__half2*)(C + (size_t)(grow + 8) * ldc + gcol) = __floats2half2_rn(d2, d3);
            } else { // OUTM == 4
                const float* rs = bias + (size_t)b * NTOK;
                const float s0 = gm / __ldg(rs + gcol);
                const float s1 = gm / __ldg(rs + gcol + 1);
                float* C = (float*)Cout + (size_t)b * sC;
                float2 c0 = *(float2*)(C + (size_t)grow * ldc + gcol);
                float2 c1 = *(float2*)(C + (size_t)(grow + 8) * ldc + gcol);
                c0.x += s0 * d0; c0.y += s1 * d1;
                c1.x += s0 * d2; c1.y += s1 * d3;
                *(float2*)(C + (size_t)grow * ldc + gcol) = c0;
                *(float2*)(C + (size_t)(grow + 8) * ldc + gcol) = c1;
            }
        }
    }
}

// transpose fp32 [b][C][1024] -> fp16 [b][1024][C]
__global__ __launch_bounds__(256) void transpose_h(
    const float* __restrict__ in, h16* __restrict__ outp, int C)
{
    __shared__ float t[32][33];
    const int c0 = blockIdx.x * 32, n0 = blockIdx.y * 32, b = blockIdx.z;
    const float* pin = in + (size_t)b * C * NTOK;
    const int tx = threadIdx.x & 31, ty = threadIdx.x >> 5;
    #pragma unroll
    for (int i = 0; i < 4; i++)
        t[ty + i * 8][tx] = pin[(size_t)(c0 + ty + i * 8) * NTOK + n0 + tx];
    __syncthreads();
    #pragma unroll
    for (int i = 0; i < 4; i++) {
        size_t o = (size_t)b * NTOK * C + (size_t)(n0 + ty + i * 8) * C + c0 + tx;
        outp[o] = __float2half_rn(t[tx][ty + i * 8]);
    }
}

// fused 512x512 weight transposes: z=0 Wc->WcT, z=1 Wk->WkT (fp16 out)
__global__ __launch_bounds__(256) void transpose_w2(
    const float* __restrict__ Wc, h16* __restrict__ WcT,
    const float* __restrict__ Wk, h16* __restrict__ WkT)
{
    const float* in = blockIdx.z ? Wk : Wc;
    h16* outp = blockIdx.z ? WkT : WcT;
    __shared__ float t[32][33];
    const int c0 = blockIdx.x * 32, r0 = blockIdx.y * 32;
    const int tx = threadIdx.x & 31, ty = threadIdx.x >> 5;
    #pragma unroll
    for (int i = 0; i < 4; i++)
        t[ty + i * 8][tx] = in[(size_t)(r0 + ty + i * 8) * HIDC + c0 + tx];
    __syncthreads();
    #pragma unroll
    for (int i = 0; i < 4; i++)
        outp[(size_t)(c0 + ty + i * 8) * HIDC + r0 + tx] = __float2half_rn(t[tx][ty + i * 8]);
}

// fused weight casts: y=0 Wq, y=1 Wk, y=2 Wv, y=3 Wc, y=4 We
__global__ void cast_weights(
    const float* __restrict__ Wq, const float* __restrict__ Wk,
    const float* __restrict__ Wv, const float* __restrict__ Wc,
    const float* __restrict__ We,
    h16* __restrict__ oq, h16* __restrict__ ok, h16* __restrict__ ov,
    h16* __restrict__ oc, h16* __restrict__ oe)
{
    const int i = blockIdx.x * 256 + threadIdx.x;
    const int w = blockIdx.y;
    if (w == 4) {
        if (i < HIDC * CEFF) oe[i] = __float2half_rn(We[i]);
        return;
    }
    if (i >= HIDC * HIDC) return;
    if (w == 0)      oq[i] = __float2half_rn(Wq[i]);
    else if (w == 1) ok[i] = __float2half_rn(Wk[i]);
    else if (w == 2) ov[i] = __float2half_rn(Wv[i]);
    else             oc[i] = __float2half_rn(Wc[i]);
}

// bqc = Wq @ bc + bq
__global__ void combine_qbias(
    const float* __restrict__ Wq, const float* __restrict__ bcnn,
    const float* __restrict__ bq, float* __restrict__ bqc)
{
    const int o = blockIdx.x * 8 + (threadIdx.x >> 5);
    const int l = threadIdx.x & 31;
    float s = 0.f;
    for (int c = l; c < HIDC; c += 32) s += Wq[(size_t)o * HIDC + c] * bcnn[c];
    #pragma unroll
    for (int d = 16; d; d >>= 1) s += __shfl_xor_sync(0xFFFFFFFFu, s, d);
    if (l == 0) bqc[o] = s + bq[o];
}

// bq2[i] = sum_a WkT[i][a] * bqc[a]   (WkT fp16, coalesced rows)
__global__ void combine_q2bias(
    const h16* __restrict__ WkT, const float* __restrict__ bqc,
    float* __restrict__ bq2)
{
    const int o = blockIdx.x * 8 + (threadIdx.x >> 5);
    const int l = threadIdx.x & 31;
    float s = 0.f;
    for (int a = l; a < HIDC; a += 32)
        s += __half2float(WkT[(size_t)o * HIDC + a]) * bqc[a];
    #pragma unroll
    for (int d = 16; d; d >>= 1) s += __shfl_xor_sync(0xFFFFFFFFu, s, d);
    if (l == 0) bq2[o] = s;
}

// ------------------------------ launch ------------------------------------
extern "C" void kernel_launch(void* const* d_in, const int* in_sizes, int n_in,
                              void* d_out, int out_size)
{
    const float* xc = (const float*)d_in[0];
    const float* xe = (const float*)d_in[1];
    const float* Wc = (const float*)d_in[2];
    const float* bc = (const float*)d_in[3];
    const float* We = (const float*)d_in[4];
    const float* be = (const float*)d_in[5];
    const float* Wq = (const float*)d_in[6];
    const float* bq = (const float*)d_in[7];
    const float* Wk = (const float*)d_in[8];
    const float* bk = (const float*)d_in[9];
    const float* Wv = (const float*)d_in[10];
    const float* bv = (const float*)d_in[11];
    const float* gamma = (const float*)d_in[12];
    float* out = (float*)d_out;
    (void)bk;  // q·bk is softmax-row-constant -> drops out exactly

    float *p_bqc, *p_bq2, *p_rsum;
    h16 *p_Wq_h, *p_Wk_h, *p_Wv_h, *p_We_h, *p_WcT, *p_WkT, *p_Wc_h, *p_WqcT, *p_Wq2;
    h16 *p_XcT, *p_XeT, *p_eff, *p_qb, *p_vb, *p_P;
    cudaGetSymbolAddress((void**)&p_bqc, g_bqc);
    cudaGetSymbolAddress((void**)&p_bq2, g_bq2);
    cudaGetSymbolAddress((void**)&p_rsum, g_rsum);
    cudaGetSymbolAddress((void**)&p_Wq_h, g_Wq_h);
    cudaGetSymbolAddress((void**)&p_Wk_h, g_Wk_h);
    cudaGetSymbolAddress((void**)&p_Wv_h, g_Wv_h);
    cudaGetSymbolAddress((void**)&p_We_h, g_We_h);
    cudaGetSymbolAddress((void**)&p_WcT, g_WcT);
    cudaGetSymbolAddress((void**)&p_WkT, g_WkT);
    cudaGetSymbolAddress((void**)&p_Wc_h, g_Wc_h);
    cudaGetSymbolAddress((void**)&p_WqcT, g_WqcT);
    cudaGetSymbolAddress((void**)&p_Wq2, g_Wq2);
    cudaGetSymbolAddress((void**)&p_XcT, g_XcT);
    cudaGetSymbolAddress((void**)&p_XeT, g_XeT);
    cudaGetSymbolAddress((void**)&p_eff, g_eff);
    cudaGetSymbolAddress((void**)&p_qb, g_qb);
    cudaGetSymbolAddress((void**)&p_vb, g_vb);
    cudaGetSymbolAddress((void**)&p_P, g_P);

    static cudaStream_t s1 = nullptr;
    static cudaEvent_t e_cast = nullptr, e_eff = nullptr, e_v = nullptr;
    if (!s1) {
        cudaStreamCreateWithFlags(&s1, cudaStreamNonBlocking);
        cudaEventCreateWithFlags(&e_cast, cudaEventDisableTiming);
        cudaEventCreateWithFlags(&e_eff, cudaEventDisableTiming);
        cudaEventCreateWithFlags(&e_v, cudaEventDisableTiming);
    }
    cudaStream_t s0 = 0;

    const int SM_PLAIN = 3 * 2 * TILEB;   // 110592
    cudaFuncSetAttribute(mma_gemm<1, 0>, cudaFuncAttributeMaxDynamicSharedMemorySize, SM_PLAIN);
    cudaFuncSetAttribute(mma_gemm<0, 1>, cudaFuncAttributeMaxDynamicSharedMemorySize, SM_PLAIN);
    cudaFuncSetAttribute(mma_gemm<2, 1>, cudaFuncAttributeMaxDynamicSharedMemorySize, SM_PLAIN);
    cudaFuncSetAttribute(mma_gemm<1, 1>, cudaFuncAttributeMaxDynamicSharedMemorySize, SM_PLAIN);
    cudaFuncSetAttribute(mma_gemm<0, 3>, cudaFuncAttributeMaxDynamicSharedMemorySize, SM_PLAIN);
    cudaFuncSetAttribute(mma_gemm<0, 4>, cudaFuncAttributeMaxDynamicSharedMemorySize, SM_PLAIN);

    const size_t sXc = (size_t)NTOK * HIDC;
    const size_t sXe = (size_t)NTOK * CEFF;
    const size_t sO  = (size_t)HIDC * NTOK;
    const size_t sAt = (size_t)NTOK * NTOK;

    // ---- s0: shared prep ----
    cast_weights<<<dim3(2560, 5), 256, 0, s0>>>(Wq, Wk, Wv, Wc, We,
        p_Wq_h, p_Wk_h, p_Wv_h, p_Wc_h, p_We_h);
    cudaEventRecord(e_cast, s0);

    // ---- s1: efficient chain ----
    cudaStreamWaitEvent(s1, e_cast, 0);
    transpose_h<<<dim3(40, 32, BATCH), 256, 0, s1>>>(xe, p_XeT, CEFF);
    mma_gemm<2, 1><<<dim3(4, 8, BATCH), 256, SM_PLAIN, s1>>>(
        p_XeT, p_We_h, CEFF, CEFF, sXe, 0, p_eff, HIDC, sXc, be, nullptr, CEFF);
    cudaEventRecord(e_eff, s1);
    mma_gemm<1, 1><<<dim3(8, 4, BATCH), 256, SM_PLAIN, s1>>>(
        p_Wv_h, p_eff, HIDC, HIDC, 0, sXc, p_vb, NTOK, sO, bv, nullptr, HIDC);
    cudaEventRecord(e_v, s1);

    // ---- s0: cnn chain + weight folds ----
    transpose_w2<<<dim3(16, 16, 2), 256, 0, s0>>>(Wc, p_WcT, Wk, p_WkT);
    combine_qbias<<<64, 256, 0, s0>>>(Wq, bc, bq, p_bqc);
    combine_q2bias<<<64, 256, 0, s0>>>(p_WkT, p_bqc, p_bq2);
    cudaMemsetAsync(p_rsum, 0, (size_t)BATCH * NTOK * sizeof(float), s0);
    // fold1: WqcT[c][a] = sum_d WcT[c][d] * Wq[a][d]
    mma_gemm<0, 1><<<dim3(4, 4, 1), 256, SM_PLAIN, s0>>>(
        p_WcT, p_Wq_h, HIDC, HIDC, 0, 0, p_WqcT, HIDC, 0, nullptr, nullptr, HIDC);
    // fold2: Wq2[i][c] = sum_a WkT[i][a] * WqcT[c][a]
    mma_gemm<0, 1><<<dim3(4, 4, 1), 256, SM_PLAIN, s0>>>(
        p_WkT, p_WqcT, HIDC, HIDC, 0, 0, p_Wq2, HIDC, 0, nullptr, nullptr, HIDC);
    transpose_h<<<dim3(16, 32, BATCH), 256, 0, s0>>>(xc, p_XcT, HIDC);
    // cnn_proj fp16 -> d_out fp32 [b][c][n]
    mma_gemm<1, 0><<<dim3(8, 4, BATCH), 256, SM_PLAIN, s0>>>(
        p_Wc_h, p_XcT, HIDC, HIDC, 0, sXc, out, NTOK, sO, bc, nullptr, HIDC);
    // q2[b][n][i] = XcT @ Wq2^T + bq2
    mma_gemm<2, 1><<<dim3(4, 8, BATCH), 256, SM_PLAIN, s0>>>(
        p_XcT, p_Wq2, HIDC, HIDC, sXc, 0, p_qb, HIDC, sXc, p_bq2, nullptr, HIDC);

    // ---- join: logits = q2 @ eff^T (k GEMM eliminated) ----
    cudaStreamWaitEvent(s0, e_eff, 0);
    mma_gemm<0, 3><<<dim3(8, 8, BATCH), 256, SM_PLAIN, s0>>>(
        p_qb, p_eff, HIDC, HIDC, sXc, sXc, p_P, NTOK, sAt, p_rsum, nullptr, HIDC);

    // PV after v ready
    cudaStreamWaitEvent(s0, e_v, 0);
    mma_gemm<0, 4><<<dim3(8, 4, BATCH), 256, SM_PLAIN, s0>>>(
        p_vb, p_P, NTOK, NTOK, sO, sAt, out, NTOK, sO, p_rsum, gamma, NTOK);
}

// round 16
// speedup vs baseline: 1.5444x; 1.1042x over previous
#include <cuda_runtime.h>
#include <cuda_fp16.h>
#include <cstdint>
#include <cstddef>

#define HIDC 512
#define NTOK 1024
#define BATCH 32
#define CEFF 1280

typedef __half h16;

// ------------------------- scratch ---------------------------------------
__device__ float g_bqc[HIDC], g_bq2[HIDC];
__device__ float g_rsum[(size_t)BATCH * NTOK];

__device__ h16 g_Wq_h[HIDC * HIDC], g_Wk_h[HIDC * HIDC], g_Wv_h[HIDC * HIDC];
__device__ h16 g_We_h[HIDC * CEFF];
__device__ h16 g_WcT[HIDC * HIDC];
__device__ h16 g_WkT[HIDC * HIDC];
__device__ h16 g_Wc_h[HIDC * HIDC];
__device__ h16 g_WqcT[HIDC * HIDC];
__device__ h16 g_Wq2[HIDC * HIDC];

__device__ h16 g_XcT[(size_t)BATCH * NTOK * HIDC];
__device__ h16 g_XeT[(size_t)BATCH * NTOK * CEFF];

__device__ h16 g_eff[(size_t)BATCH * NTOK * HIDC];
__device__ h16 g_qb[(size_t)BATCH * NTOK * HIDC];
__device__ h16 g_vb[(size_t)BATCH * HIDC * NTOK];
__device__ h16 g_P[(size_t)BATCH * NTOK * NTOK];

#define MMA_F16(D, A_, B_) \
    asm volatile("mma.sync.aligned.m16n8k16.row.col.f32.f16.f16.f32 " \
        "{%0,%1,%2,%3}, {%4,%5,%6,%7}, {%8,%9}, {%0,%1,%2,%3};" \
        : "+f"((D)[0]), "+f"((D)[1]), "+f"((D)[2]), "+f"((D)[3]) \
        : "r"((A_)[0]), "r"((A_)[1]), "r"((A_)[2]), "r"((A_)[3]), \
          "r"((B_)[0]), "r"((B_)[1]))

#define LDSM4(R0, R1, R2, R3, ADDR) \
    asm volatile("ldmatrix.sync.aligned.m8n8.x4.shared.b16 {%0,%1,%2,%3}, [%4];" \
        : "=r"(R0), "=r"(R1), "=r"(R2), "=r"(R3) : "r"(ADDR))

__device__ __forceinline__ uint32_t smem_u32(const void* p) {
    uint32_t a;
    asm("{ .reg .u64 t; cvta.to.shared.u64 t, %1; cvt.u32.u64 %0, t; }" : "=r"(a) : "l"(p));
    return a;
}
__device__ __forceinline__ void cp16(uint32_t dst, const void* src) {
    asm volatile("cp.async.cg.shared.global [%0], [%1], 16;" :: "r"(dst), "l"(src));
}
__device__ __forceinline__ void cp_commit() {
    asm volatile("cp.async.commit_group;" ::: "memory");
}
template<int N> __device__ __forceinline__ void cp_wait() {
    asm volatile("cp.async.wait_group %0;" :: "n"(N) : "memory");
}

#define TILEB 18432   // 128 rows * 72 elems * 2B

// ---------------------------------------------------------------------------
// fp16 HMMA GEMM, 3-stage cp.async pipeline, BK=64, ldmatrix fragments.
// C[M0+128, N0+128] = sum_K A[m,k] * B[n,k]  (both K-major)
// BIASM: 0 none, 1 bias[row], 2 bias[col]
// OUTM: 0 fp32 row-major (+bias) | 1 fp16 row-major (+bias)
//       3 fp16 exp(D) + rowsum atomics | 4 fp32 RMW += gamma/rowsum[col]*D
// ---------------------------------------------------------------------------
template<int BIASM, int OUTM>
__global__ __launch_bounds__(256) void mma_gemm(
    const h16* __restrict__ A, const h16* __restrict__ B,
    int lda, int ldb, size_t sA, size_t sB,
    void* __restrict__ Cout, int ldc, size_t sC,
    const float* __restrict__ bias, const float* __restrict__ gamma, int K)
{
    extern __shared__ char dynsm[];
    constexpr int STAGE = 2 * TILEB;
    const uint32_t sm0 = smem_u32(dynsm);

    const int tid = threadIdx.x;
    const int wid = tid >> 5;
    const int lid = tid & 31;
    const int wm = wid & 1;
    const int wn = wid >> 1;
    const int g  = lid >> 2;
    const int tc = (lid & 3) * 2;

    const int M0 = blockIdx.y * 128;
    const int N0 = blockIdx.x * 128;
    const int b  = blockIdx.z;

    const h16* pA = A + (size_t)b * sA + (size_t)M0 * lda;
    const h16* pB = B + (size_t)b * sB + (size_t)N0 * ldb;

    const int l8  = lid & 7;
    const int mi1 = (lid >> 3) & 1;
    const int mi2 = (lid >> 4) & 1;
    const uint32_t offA = (uint32_t)(((wm * 64 + mi1 * 8 + l8) * 72 + mi2 * 8) * 2);
    const uint32_t offB = (uint32_t)(((wn * 32 + mi2 * 8 + l8) * 72 + mi1 * 8) * 2);

    float acc[4][4][4];
    #pragma unroll
    for (int i = 0; i < 4; i++)
        #pragma unroll
        for (int j = 0; j < 4; j++)
            #pragma unroll
            for (int r = 0; r < 4; r++) acc[i][j][r] = 0.f;

    const int nk = K >> 6;

    auto copy_stage = [&](int buf, int kt) {
        const int k0 = kt << 6;
        const uint32_t sb = sm0 + buf * STAGE;
        #pragma unroll
        for (int s = 0; s < 4; s++) {
            const int i = tid + s * 256;
            const int r = i >> 3, c = (i & 7) * 8;
            const uint32_t so = (uint32_t)((r * 72 + c) * 2);
            cp16(sb + so,         pA + (size_t)r * lda + k0 + c);
            cp16(sb + TILEB + so, pB + (size_t)r * ldb + k0 + c);
        }
        cp_commit();
    };

    copy_stage(0, 0);
    copy_stage(1, 1);

    int buf = 0;
    for (int kt = 0; kt < nk; kt++) {
        if (kt + 2 < nk) {
            int nb = buf + 2; if (nb >= 3) nb -= 3;
            copy_stage(nb, kt + 2);
            cp_wait<2>();
        } else if (kt + 1 < nk) {
            cp_wait<1>();
        } else {
            cp_wait<0>();
        }
        __syncthreads();

        const uint32_t sb = sm0 + buf * STAGE;
        #pragma unroll
        for (int ks = 0; ks < 64; ks += 16) {
            uint32_t a[4][4], bb[4][2];
            #pragma unroll
            for (int mt = 0; mt < 4; mt++)
                LDSM4(a[mt][0], a[mt][1], a[mt][2], a[mt][3],
                      sb + offA + mt * 2304 + ks * 2);
            #pragma unroll
            for (int p = 0; p < 2; p++)
                LDSM4(bb[2 * p][0], bb[2 * p][1], bb[2 * p + 1][0], bb[2 * p + 1][1],
                      sb + TILEB + offB + p * 2304 + ks * 2);
            #pragma unroll
            for (int mt = 0; mt < 4; mt++)
                #pragma unroll
                for (int nt = 0; nt < 4; nt++)
                    MMA_F16(acc[mt][nt], a[mt], bb[nt]);
        }
        __syncthreads();
        if (++buf == 3) buf = 0;
    }

    // ---------------- epilogue ----------------
    if (OUTM == 3) {
        __shared__ float srow[128];
        float* rs = const_cast<float*>(bias) + (size_t)b * NTOK;
        if (tid < 128) srow[tid] = 0.f;
        __syncthreads();
        h16* C = (h16*)Cout + (size_t)b * sC;
        #pragma unroll
        for (int mt = 0; mt < 4; mt++) {
            const int grow = M0 + wm * 64 + mt * 16 + g;
            float rp0 = 0.f, rp1 = 0.f;
            #pragma unroll
            for (int nt = 0; nt < 4; nt++) {
                const int gcol = N0 + wn * 32 + nt * 8 + tc;
                float e0 = __expf(acc[mt][nt][0]);
                float e1 = __expf(acc[mt][nt][1]);
                float e2 = __expf(acc[mt][nt][2]);
                float e3 = __expf(acc[mt][nt][3]);
                *(__half2*)(C + (size_t)grow * ldc + gcol) = __floats2half2_rn(e0, e1);
                *(__half2*)(C + (size_t)(grow + 8) * ldc + gcol) = __floats2half2_rn(e2, e3);
                rp0 += e0 + e1;
                rp1 += e2 + e3;
            }
            rp0 += __shfl_xor_sync(0xFFFFFFFFu, rp0, 1);
            rp0 += __shfl_xor_sync(0xFFFFFFFFu, rp0, 2);
            rp1 += __shfl_xor_sync(0xFFFFFFFFu, rp1, 1);
            rp1 += __shfl_xor_sync(0xFFFFFFFFu, rp1, 2);
            if ((lid & 3) == 0) {
                atomicAdd(&srow[wm * 64 + mt * 16 + g], rp0);
                atomicAdd(&srow[wm * 64 + mt * 16 + 8 + g], rp1);
            }
        }
        __syncthreads();
        if (tid < 128) atomicAdd(rs + M0 + tid, srow[tid]);
        return;
    }

    const float gm = (OUTM == 4) ? gamma[0] : 0.f;
    #pragma unroll
    for (int mt = 0; mt < 4; mt++) {
        #pragma unroll
        for (int nt = 0; nt < 4; nt++) {
            const int grow = M0 + wm * 64 + mt * 16 + g;
            const int gcol = N0 + wn * 32 + nt * 8 + tc;
            float d0 = acc[mt][nt][0], d1 = acc[mt][nt][1];
            float d2 = acc[mt][nt][2], d3 = acc[mt][nt][3];

            if (OUTM == 0 || OUTM == 1) {
                if (BIASM == 1) {
                    float br0 = __ldg(bias + grow), br1 = __ldg(bias + grow + 8);
                    d0 += br0; d1 += br0; d2 += br1; d3 += br1;
                } else if (BIASM == 2) {
                    float bc0 = __ldg(bias + gcol), bc1 = __ldg(bias + gcol + 1);
                    d0 += bc0; d1 += bc1; d2 += bc0; d3 += bc1;
                }
            }

            if (OUTM == 0) {
                float* C = (float*)Cout + (size_t)b * sC;
                *(float2*)(C + (size_t)grow * ldc + gcol) = make_float2(d0, d1);
                *(float2*)(C + (size_t)(grow + 8) * ldc + gcol) = make_float2(d2, d3);
            } else if (OUTM == 1) {
                h16* C = (h16*)Cout + (size_t)b * sC;
                *(__half2*)(C + (size_t)grow * ldc + gcol) = __floats2half2_rn(d0, d1);
                *(__half2*)(C + (size_t)(grow + 8) * ldc + gcol) = __floats2half2_rn(d2, d3);
            } else { // OUTM == 4
                const float* rs = bias + (size_t)b * NTOK;
                const float s0 = gm / __ldg(rs + gcol);
                const float s1 = gm / __ldg(rs + gcol + 1);
                float* C = (float*)Cout + (size_t)b * sC;
                float2 c0 = *(float2*)(C + (size_t)grow * ldc + gcol);
                float2 c1 = *(float2*)(C + (size_t)(grow + 8) * ldc + gcol);
                c0.x += s0 * d0; c0.y += s1 * d1;
                c1.x += s0 * d2; c1.y += s1 * d3;
                *(float2*)(C + (size_t)grow * ldc + gcol) = c0;
                *(float2*)(C + (size_t)(grow + 8) * ldc + gcol) = c1;
            }
        }
    }
}

// transpose fp32 [b][C][1024] -> fp16 [b][1024][C]
__global__ __launch_bounds__(256) void transpose_h(
    const float* __restrict__ in, h16* __restrict__ outp, int C)
{
    __shared__ float t[32][33];
    const int c0 = blockIdx.x * 32, n0 = blockIdx.y * 32, b = blockIdx.z;
    const float* pin = in + (size_t)b * C * NTOK;
    const int tx = threadIdx.x & 31, ty = threadIdx.x >> 5;
    #pragma unroll
    for (int i = 0; i < 4; i++)
        t[ty + i * 8][tx] = pin[(size_t)(c0 + ty + i * 8) * NTOK + n0 + tx];
    __syncthreads();
    #pragma unroll
    for (int i = 0; i < 4; i++) {
        size_t o = (size_t)b * NTOK * C + (size_t)(n0 + ty + i * 8) * C + c0 + tx;
        outp[o] = __float2half_rn(t[tx][ty + i * 8]);
    }
}

// fused 512x512 weight transposes: z=0 Wc->WcT, z=1 Wk->WkT (fp16 out)
__global__ __launch_bounds__(256) void transpose_w2(
    const float* __restrict__ Wc, h16* __restrict__ WcT,
    const float* __restrict__ Wk, h16* __restrict__ WkT)
{
    const float* in = blockIdx.z ? Wk : Wc;
    h16* outp = blockIdx.z ? WkT : WcT;
    __shared__ float t[32][33];
    const int c0 = blockIdx.x * 32, r0 = blockIdx.y * 32;
    const int tx = threadIdx.x & 31, ty = threadIdx.x >> 5;
    #pragma unroll
    for (int i = 0; i < 4; i++)
        t[ty + i * 8][tx] = in[(size_t)(r0 + ty + i * 8) * HIDC + c0 + tx];
    __syncthreads();
    #pragma unroll
    for (int i = 0; i < 4; i++)
        outp[(size_t)(c0 + ty + i * 8) * HIDC + r0 + tx] = __float2half_rn(t[tx][ty + i * 8]);
}

// vectorized weight casts (4 elems/thread): y=0 Wq, 1 Wk, 2 Wv, 3 Wc, 4 We
__global__ void cast_weights(
    const float* __restrict__ Wq, const float* __restrict__ Wk,
    const float* __restrict__ Wv, const float* __restrict__ Wc,
    const float* __restrict__ We,
    h16* __restrict__ oq, h16* __restrict__ ok, h16* __restrict__ ov,
    h16* __restrict__ oc, h16* __restrict__ oe)
{
    const int i4 = blockIdx.x * 256 + threadIdx.x;   // float4 index
    const int w = blockIdx.y;
    const float* src; h16* dst; int n4;
    if (w == 4)      { src = We; dst = oe; n4 = HIDC * CEFF / 4; }
    else if (w == 0) { src = Wq; dst = oq; n4 = HIDC * HIDC / 4; }
    else if (w == 1) { src = Wk; dst = ok; n4 = HIDC * HIDC / 4; }
    else if (w == 2) { src = Wv; dst = ov; n4 = HIDC * HIDC / 4; }
    else             { src = Wc; dst = oc; n4 = HIDC * HIDC / 4; }
    if (i4 >= n4) return;
    float4 v = ((const float4*)src)[i4];
    __half2 h0 = __floats2half2_rn(v.x, v.y);
    __half2 h1 = __floats2half2_rn(v.z, v.w);
    uint2 o; o.x = *(uint32_t*)&h0; o.y = *(uint32_t*)&h1;
    ((uint2*)dst)[i4] = o;
}

// bqc = Wq @ bc + bq
__global__ void combine_qbias(
    const float* __restrict__ Wq, const float* __restrict__ bcnn,
    const float* __restrict__ bq, float* __restrict__ bqc)
{
    const int o = blockIdx.x * 8 + (threadIdx.x >> 5);
    const int l = threadIdx.x & 31;
    float s = 0.f;
    for (int c = l; c < HIDC; c += 32) s += Wq[(size_t)o * HIDC + c] * bcnn[c];
    #pragma unroll
    for (int d = 16; d; d >>= 1) s += __shfl_xor_sync(0xFFFFFFFFu, s, d);
    if (l == 0) bqc[o] = s + bq[o];
}

// bq2[i] = sum_a WkT[i][a] * bqc[a]
__global__ void combine_q2bias(
    const h16* __restrict__ WkT, const float* __restrict__ bqc,
    float* __restrict__ bq2)
{
    const int o = blockIdx.x * 8 + (threadIdx.x >> 5);
    const int l = threadIdx.x & 31;
    float s = 0.f;
    for (int a = l; a < HIDC; a += 32)
        s += __half2float(WkT[(size_t)o * HIDC + a]) * bqc[a];
    #pragma unroll
    for (int d = 16; d; d >>= 1) s += __shfl_xor_sync(0xFFFFFFFFu, s, d);
    if (l == 0) bq2[o] = s;
}

// ------------------------------ launch ------------------------------------
extern "C" void kernel_launch(void* const* d_in, const int* in_sizes, int n_in,
                              void* d_out, int out_size)
{
    const float* xc = (const float*)d_in[0];
    const float* xe = (const float*)d_in[1];
    const float* Wc = (const float*)d_in[2];
    const float* bc = (const float*)d_in[3];
    const float* We = (const float*)d_in[4];
    const float* be = (const float*)d_in[5];
    const float* Wq = (const float*)d_in[6];
    const float* bq = (const float*)d_in[7];
    const float* Wk = (const float*)d_in[8];
    const float* bk = (const float*)d_in[9];
    const float* Wv = (const float*)d_in[10];
    const float* bv = (const float*)d_in[11];
    const float* gamma = (const float*)d_in[12];
    float* out = (float*)d_out;
    (void)bk;  // q·bk is softmax-row-constant -> drops out exactly

    float *p_bqc, *p_bq2, *p_rsum;
    h16 *p_Wq_h, *p_Wk_h, *p_Wv_h, *p_We_h, *p_WcT, *p_WkT, *p_Wc_h, *p_WqcT, *p_Wq2;
    h16 *p_XcT, *p_XeT, *p_eff, *p_qb, *p_vb, *p_P;
    cudaGetSymbolAddress((void**)&p_bqc, g_bqc);
    cudaGetSymbolAddress((void**)&p_bq2, g_bq2);
    cudaGetSymbolAddress((void**)&p_rsum, g_rsum);
    cudaGetSymbolAddress((void**)&p_Wq_h, g_Wq_h);
    cudaGetSymbolAddress((void**)&p_Wk_h, g_Wk_h);
    cudaGetSymbolAddress((void**)&p_Wv_h, g_Wv_h);
    cudaGetSymbolAddress((void**)&p_We_h, g_We_h);
    cudaGetSymbolAddress((void**)&p_WcT, g_WcT);
    cudaGetSymbolAddress((void**)&p_WkT, g_WkT);
    cudaGetSymbolAddress((void**)&p_Wc_h, g_Wc_h);
    cudaGetSymbolAddress((void**)&p_WqcT, g_WqcT);
    cudaGetSymbolAddress((void**)&p_Wq2, g_Wq2);
    cudaGetSymbolAddress((void**)&p_XcT, g_XcT);
    cudaGetSymbolAddress((void**)&p_XeT, g_XeT);
    cudaGetSymbolAddress((void**)&p_eff, g_eff);
    cudaGetSymbolAddress((void**)&p_qb, g_qb);
    cudaGetSymbolAddress((void**)&p_vb, g_vb);
    cudaGetSymbolAddress((void**)&p_P, g_P);

    static cudaStream_t s1 = nullptr;
    static cudaEvent_t e_cast = nullptr, e_eff = nullptr, e_v = nullptr;
    static cudaEvent_t e_q2 = nullptr, e_cnn = nullptr, e_l1 = nullptr;
    if (!s1) {
        cudaStreamCreateWithFlags(&s1, cudaStreamNonBlocking);
        cudaEventCreateWithFlags(&e_cast, cudaEventDisableTiming);
        cudaEventCreateWithFlags(&e_eff, cudaEventDisableTiming);
        cudaEventCreateWithFlags(&e_v, cudaEventDisableTiming);
        cudaEventCreateWithFlags(&e_q2, cudaEventDisableTiming);
        cudaEventCreateWithFlags(&e_cnn, cudaEventDisableTiming);
        cudaEventCreateWithFlags(&e_l1, cudaEventDisableTiming);
    }
    cudaStream_t s0 = 0;

    const int SM_PLAIN = 3 * 2 * TILEB;   // 110592
    cudaFuncSetAttribute(mma_gemm<1, 0>, cudaFuncAttributeMaxDynamicSharedMemorySize, SM_PLAIN);
    cudaFuncSetAttribute(mma_gemm<0, 1>, cudaFuncAttributeMaxDynamicSharedMemorySize, SM_PLAIN);
    cudaFuncSetAttribute(mma_gemm<2, 1>, cudaFuncAttributeMaxDynamicSharedMemorySize, SM_PLAIN);
    cudaFuncSetAttribute(mma_gemm<1, 1>, cudaFuncAttributeMaxDynamicSharedMemorySize, SM_PLAIN);
    cudaFuncSetAttribute(mma_gemm<0, 3>, cudaFuncAttributeMaxDynamicSharedMemorySize, SM_PLAIN);
    cudaFuncSetAttribute(mma_gemm<0, 4>, cudaFuncAttributeMaxDynamicSharedMemorySize, SM_PLAIN);

    const size_t sXc = (size_t)NTOK * HIDC;
    const size_t sXe = (size_t)NTOK * CEFF;
    const size_t sO  = (size_t)HIDC * NTOK;
    const size_t sAt = (size_t)NTOK * NTOK;
    const int HB = BATCH / 2;   // batch half

    // ---- t=0: xe transpose on s1 (no dependencies), cast on s0 ----
    transpose_h<<<dim3(40, 32, BATCH), 256, 0, s1>>>(xe, p_XeT, CEFF);
    cast_weights<<<dim3(640, 5), 256, 0, s0>>>(Wq, Wk, Wv, Wc, We,
        p_Wq_h, p_Wk_h, p_Wv_h, p_Wc_h, p_We_h);
    cudaEventRecord(e_cast, s0);

    // ---- s1: eff + v (needs We/Wv casts) ----
    cudaStreamWaitEvent(s1, e_cast, 0);
    mma_gemm<2, 1><<<dim3(4, 8, BATCH), 256, SM_PLAIN, s1>>>(
        p_XeT, p_We_h, CEFF, CEFF, sXe, 0, p_eff, HIDC, sXc, be, nullptr, CEFF);
    cudaEventRecord(e_eff, s1);
    mma_gemm<1, 1><<<dim3(8, 4, BATCH), 256, SM_PLAIN, s1>>>(
        p_Wv_h, p_eff, HIDC, HIDC, 0, sXc, p_vb, NTOK, sO, bv, nullptr, HIDC);
    cudaEventRecord(e_v, s1);

    // ---- s0: folds + cnn chain ----
    transpose_w2<<<dim3(16, 16, 2), 256, 0, s0>>>(Wc, p_WcT, Wk, p_WkT);
    combine_qbias<<<64, 256, 0, s0>>>(Wq, bc, bq, p_bqc);
    combine_q2bias<<<64, 256, 0, s0>>>(p_WkT, p_bqc, p_bq2);
    cudaMemsetAsync(p_rsum, 0, (size_t)BATCH * NTOK * sizeof(float), s0);
    mma_gemm<0, 1><<<dim3(4, 4, 1), 256, SM_PLAIN, s0>>>(
        p_WcT, p_Wq_h, HIDC, HIDC, 0, 0, p_WqcT, HIDC, 0, nullptr, nullptr, HIDC);
    mma_gemm<0, 1><<<dim3(4, 4, 1), 256, SM_PLAIN, s0>>>(
        p_WkT, p_WqcT, HIDC, HIDC, 0, 0, p_Wq2, HIDC, 0, nullptr, nullptr, HIDC);
    transpose_h<<<dim3(16, 32, BATCH), 256, 0, s0>>>(xc, p_XcT, HIDC);
    mma_gemm<1, 0><<<dim3(8, 4, BATCH), 256, SM_PLAIN, s0>>>(
        p_Wc_h, p_XcT, HIDC, HIDC, 0, sXc, out, NTOK, sO, bc, nullptr, HIDC);
    cudaEventRecord(e_cnn, s0);
    mma_gemm<2, 1><<<dim3(4, 8, BATCH), 256, SM_PLAIN, s0>>>(
        p_XcT, p_Wq2, HIDC, HIDC, sXc, 0, p_qb, HIDC, sXc, p_bq2, nullptr, HIDC);
    cudaEventRecord(e_q2, s0);

    // ---- batch-split attention tail across both streams ----
    // logits half 0 (batches 0..15) on s0
    cudaStreamWaitEvent(s0, e_eff, 0);
    mma_gemm<0, 3><<<dim3(8, 8, HB), 256, SM_PLAIN, s0>>>(
        p_qb, p_eff, HIDC, HIDC, sXc, sXc, p_P, NTOK, sAt, p_rsum, nullptr, HIDC);

    // logits half 1 (batches 16..31) on s1 (after v on s1; q2 from s0)
    cudaStreamWaitEvent(s1, e_q2, 0);
    mma_gemm<0, 3><<<dim3(8, 8, HB), 256, SM_PLAIN, s1>>>(
        p_qb + (size_t)HB * sXc, p_eff + (size_t)HB * sXc, HIDC, HIDC, sXc, sXc,
        p_P + (size_t)HB * sAt, NTOK, sAt, p_rsum + (size_t)HB * NTOK, nullptr, HIDC);
    cudaEventRecord(e_l1, s1);

    // PV half 0 on s0 (needs v from s1)
    cudaStreamWaitEvent(s0, e_v, 0);
    mma_gemm<0, 4><<<dim3(8, 4, HB), 256, SM_PLAIN, s0>>>(
        p_vb, p_P, NTOK, NTOK, sO, sAt,
        out, NTOK, sO, p_rsum, gamma, NTOK);

    // PV half 1 on s1 (needs cnn from s0; logits1 + v already on s1)
    cudaStreamWaitEvent(s1, e_cnn, 0);
    mma_gemm<0, 4><<<dim3(8, 4, HB), 256, SM_PLAIN, s1>>>(
        p_vb + (size_t)HB * sO, p_P + (size_t)HB * sAt, NTOK, NTOK, sO, sAt,
        out + (size_t)HB * sO, NTOK, sO, p_rsum + (size_t)HB * NTOK, gamma, NTOK);

    // rejoin: s0 must not signal completion before s1's PV half finishes
    cudaStreamWaitEvent(s0, e_l1, 0);
    cudaEventRecord(e_l1, s1);
    cudaStreamWaitEvent(s0, e_l1, 0);
}